// round 1
// baseline (speedup 1.0000x reference)
#include <cuda_runtime.h>

#define BB 4
#define SS 2048
#define HH 16
#define DKK 64
#define DD 1024
#define MR (BB*SS)        // 8192 rows

// Scratch: Q,K,V,attn-out in [B,H,S,64] layout (device globals; no allocs)
__device__ float g_Q[(size_t)BB*HH*SS*DKK];
__device__ float g_K[(size_t)BB*HH*SS*DKK];
__device__ float g_V[(size_t)BB*HH*SS*DKK];
__device__ float g_A[(size_t)BB*HH*SS*DKK];

// ---------------------------------------------------------------------------
// Kernel 1: fused QKV projection.  Y = X @ W^T + b, written as [B,H,S,64].
// BM=BN=128, BK=16, 256 threads, 8x8 register tile per thread.
// ---------------------------------------------------------------------------
__global__ __launch_bounds__(256) void qkv_proj_kernel(
    const float* __restrict__ Xq, const float* __restrict__ Xk, const float* __restrict__ Xv,
    const float* __restrict__ Wq_, const float* __restrict__ Wk_, const float* __restrict__ Wv_,
    const float* __restrict__ bq, const float* __restrict__ bk, const float* __restrict__ bv)
{
    __shared__ float Xs[16][132];   // [k][m]  (transposed tiles, padded)
    __shared__ float Ws[16][132];   // [k][n]

    const float *X, *W, *bias; float* out;
    if (blockIdx.z == 0)      { X = Xq; W = Wq_; bias = bq; out = g_Q; }
    else if (blockIdx.z == 1) { X = Xk; W = Wk_; bias = bk; out = g_K; }
    else                      { X = Xv; W = Wv_; bias = bv; out = g_V; }

    const int tid = threadIdx.x;
    const int tx = tid & 15, ty = tid >> 4;
    const int bm = blockIdx.y * 128;
    const int bn = blockIdx.x * 128;
    const int lr = tid >> 2;            // 0..63
    const int lc = (tid & 3) << 2;      // 0,4,8,12

    float acc[8][8];
    #pragma unroll
    for (int i = 0; i < 8; i++)
        #pragma unroll
        for (int j = 0; j < 8; j++) acc[i][j] = 0.f;

    for (int k0 = 0; k0 < DD; k0 += 16) {
        #pragma unroll
        for (int rr = 0; rr < 2; rr++) {
            int row = lr + rr * 64;
            float4 xv = *(const float4*)(X + (size_t)(bm + row) * DD + k0 + lc);
            Xs[lc+0][row] = xv.x; Xs[lc+1][row] = xv.y;
            Xs[lc+2][row] = xv.z; Xs[lc+3][row] = xv.w;
            float4 wv = *(const float4*)(W + (size_t)(bn + row) * DD + k0 + lc);
            Ws[lc+0][row] = wv.x; Ws[lc+1][row] = wv.y;
            Ws[lc+2][row] = wv.z; Ws[lc+3][row] = wv.w;
        }
        __syncthreads();
        #pragma unroll
        for (int kk = 0; kk < 16; kk++) {
            float a[8], b[8];
            #pragma unroll
            for (int i = 0; i < 4; i++) {
                a[i]   = Xs[kk][ty*4 + i];
                a[i+4] = Xs[kk][64 + ty*4 + i];
                b[i]   = Ws[kk][tx*4 + i];
                b[i+4] = Ws[kk][64 + tx*4 + i];
            }
            #pragma unroll
            for (int i = 0; i < 8; i++)
                #pragma unroll
                for (int j = 0; j < 8; j++)
                    acc[i][j] += a[i] * b[j];
        }
        __syncthreads();
    }

    // epilogue: scatter into [B,H,S,64]
    #pragma unroll
    for (int ii = 0; ii < 8; ii++) {
        int rl = ty*4 + (ii & 3) + ((ii >> 2) << 6);
        int gr = bm + rl;
        int b_i = gr >> 11;        // / S
        int s_i = gr & 2047;       // % S
        #pragma unroll
        for (int jg = 0; jg < 2; jg++) {
            int col = bn + tx*4 + (jg << 6);
            int h = col >> 6, d = col & 63;
            float4 o;
            o.x = acc[ii][jg*4+0] + bias[col+0];
            o.y = acc[ii][jg*4+1] + bias[col+1];
            o.z = acc[ii][jg*4+2] + bias[col+2];
            o.w = acc[ii][jg*4+3] + bias[col+3];
            *(float4*)(out + (((size_t)(b_i*HH + h)*SS + s_i)*DKK + d)) = o;
        }
    }
}

// ---------------------------------------------------------------------------
// Kernel 2: flash-style attention per (b,h).  BM=64 queries, BN=64 keys/iter.
// 256 threads (16x16), 4x4 per thread. Online softmax, O = softmax(QK^T/8)V.
// ---------------------------------------------------------------------------
#define ATTN_SMEM_FLOATS (4*64*68 + 192)
#define ATTN_SMEM_BYTES  (ATTN_SMEM_FLOATS * 4)

__global__ __launch_bounds__(256) void attn_kernel()
{
    extern __shared__ float sm[];
    float (*Qt)[68] = (float(*)[68])sm;               // [k][qrow]   transposed
    float (*Kt)[68] = (float(*)[68])(sm + 64*68);     // [k][krow]   transposed
    float (*Vs)[68] = (float(*)[68])(sm + 2*64*68);   // [krow][d]
    float (*Ps)[68] = (float(*)[68])(sm + 3*64*68);   // [qrow][krow]
    float* m_s = sm + 4*64*68;
    float* l_s = m_s + 64;
    float* f_s = m_s + 128;

    const int tid = threadIdx.x;
    const int tx = tid & 15, ty = tid >> 4;
    const int bh = blockIdx.y;
    const int q0 = blockIdx.x * 64;
    const float* Qp = g_Q + (size_t)bh * SS * DKK;
    const float* Kp = g_K + (size_t)bh * SS * DKK;
    const float* Vp = g_V + (size_t)bh * SS * DKK;
    float* Ap = g_A + (size_t)bh * SS * DKK;

    if (tid < 64) { m_s[tid] = -1e30f; l_s[tid] = 0.f; }

    // load Q tile (transposed into smem)
    #pragma unroll
    for (int ii = 0; ii < 4; ii++) {
        int f = tid + 256*ii;
        int r = f >> 4, c = (f & 15) << 2;
        float4 v = *(const float4*)(Qp + (size_t)(q0 + r)*DKK + c);
        Qt[c+0][r] = v.x; Qt[c+1][r] = v.y; Qt[c+2][r] = v.z; Qt[c+3][r] = v.w;
    }
    __syncthreads();

    float acc[4][4];
    #pragma unroll
    for (int i = 0; i < 4; i++)
        #pragma unroll
        for (int j = 0; j < 4; j++) acc[i][j] = 0.f;

    for (int kb = 0; kb < SS/64; kb++) {
        const float* Kb = Kp + (size_t)kb*64*DKK;
        const float* Vb = Vp + (size_t)kb*64*DKK;
        #pragma unroll
        for (int ii = 0; ii < 4; ii++) {
            int f = tid + 256*ii;
            int r = f >> 4, c = (f & 15) << 2;
            float4 kv = *(const float4*)(Kb + (size_t)r*DKK + c);
            Kt[c+0][r] = kv.x; Kt[c+1][r] = kv.y; Kt[c+2][r] = kv.z; Kt[c+3][r] = kv.w;
            *(float4*)&Vs[r][c] = *(const float4*)(Vb + (size_t)r*DKK + c);
        }
        __syncthreads();

        // S = Q K^T  (scores)
        float s[4][4];
        #pragma unroll
        for (int i = 0; i < 4; i++)
            #pragma unroll
            for (int j = 0; j < 4; j++) s[i][j] = 0.f;

        #pragma unroll 8
        for (int k = 0; k < 64; k++) {
            float4 aa = *(const float4*)&Qt[k][ty*4];
            float4 bb = *(const float4*)&Kt[k][tx*4];
            float a_[4] = {aa.x, aa.y, aa.z, aa.w};
            float b_[4] = {bb.x, bb.y, bb.z, bb.w};
            #pragma unroll
            for (int i = 0; i < 4; i++)
                #pragma unroll
                for (int j = 0; j < 4; j++)
                    s[i][j] += a_[i] * b_[j];
        }
        #pragma unroll
        for (int i = 0; i < 4; i++) {
            float4 o = make_float4(s[i][0]*0.125f, s[i][1]*0.125f,
                                   s[i][2]*0.125f, s[i][3]*0.125f);
            *(float4*)&Ps[ty*4+i][tx*4] = o;
        }
        __syncthreads();

        // online softmax: one thread per query row
        if (tid < 64) {
            int r = tid;
            float mo = m_s[r];
            float mx = mo;
            #pragma unroll 8
            for (int j = 0; j < 64; j++) mx = fmaxf(mx, Ps[r][j]);
            float fac = __expf(mo - mx);
            float sum = 0.f;
            #pragma unroll 8
            for (int j = 0; j < 64; j++) {
                float p = __expf(Ps[r][j] - mx);
                Ps[r][j] = p;
                sum += p;
            }
            m_s[r] = mx;
            l_s[r] = l_s[r]*fac + sum;
            f_s[r] = fac;
        }
        __syncthreads();

        // rescale accumulators
        float fi[4];
        #pragma unroll
        for (int i = 0; i < 4; i++) fi[i] = f_s[ty*4+i];
        #pragma unroll
        for (int i = 0; i < 4; i++)
            #pragma unroll
            for (int j = 0; j < 4; j++) acc[i][j] *= fi[i];

        // acc += P V
        #pragma unroll 8
        for (int j = 0; j < 64; j++) {
            float4 vv = *(const float4*)&Vs[j][tx*4];
            float p0 = Ps[ty*4+0][j];
            float p1 = Ps[ty*4+1][j];
            float p2 = Ps[ty*4+2][j];
            float p3 = Ps[ty*4+3][j];
            acc[0][0] += p0*vv.x; acc[0][1] += p0*vv.y; acc[0][2] += p0*vv.z; acc[0][3] += p0*vv.w;
            acc[1][0] += p1*vv.x; acc[1][1] += p1*vv.y; acc[1][2] += p1*vv.z; acc[1][3] += p1*vv.w;
            acc[2][0] += p2*vv.x; acc[2][1] += p2*vv.y; acc[2][2] += p2*vv.z; acc[2][3] += p2*vv.w;
            acc[3][0] += p3*vv.x; acc[3][1] += p3*vv.y; acc[3][2] += p3*vv.z; acc[3][3] += p3*vv.w;
        }
        __syncthreads();
    }

    #pragma unroll
    for (int i = 0; i < 4; i++) {
        float inv = 1.f / l_s[ty*4+i];
        float4 o = make_float4(acc[i][0]*inv, acc[i][1]*inv, acc[i][2]*inv, acc[i][3]*inv);
        *(float4*)(Ap + (size_t)(q0 + ty*4+i)*DKK + tx*4) = o;
    }
}

// ---------------------------------------------------------------------------
// Kernel 3: output projection.  out[B,S,D] = gather(g_A) @ Wo^T + bo
// ---------------------------------------------------------------------------
__global__ __launch_bounds__(256) void out_proj_kernel(
    const float* __restrict__ Wo, const float* __restrict__ bo, float* __restrict__ out)
{
    __shared__ float Xs[16][132];
    __shared__ float Ws[16][132];
    const int tid = threadIdx.x;
    const int tx = tid & 15, ty = tid >> 4;
    const int bm = blockIdx.y * 128;
    const int bn = blockIdx.x * 128;
    const int lr = tid >> 2;
    const int lc = (tid & 3) << 2;

    float acc[8][8];
    #pragma unroll
    for (int i = 0; i < 8; i++)
        #pragma unroll
        for (int j = 0; j < 8; j++) acc[i][j] = 0.f;

    for (int k0 = 0; k0 < DD; k0 += 16) {
        #pragma unroll
        for (int rr = 0; rr < 2; rr++) {
            int row = lr + rr * 64;
            int gr = bm + row;
            int b_i = gr >> 11, s_i = gr & 2047;
            int kg = k0 + lc;
            int h = kg >> 6, d = kg & 63;
            float4 xv = *(const float4*)(g_A + (((size_t)(b_i*HH + h)*SS + s_i)*DKK + d));
            Xs[lc+0][row] = xv.x; Xs[lc+1][row] = xv.y;
            Xs[lc+2][row] = xv.z; Xs[lc+3][row] = xv.w;
            float4 wv = *(const float4*)(Wo + (size_t)(bn + row) * DD + k0 + lc);
            Ws[lc+0][row] = wv.x; Ws[lc+1][row] = wv.y;
            Ws[lc+2][row] = wv.z; Ws[lc+3][row] = wv.w;
        }
        __syncthreads();
        #pragma unroll
        for (int kk = 0; kk < 16; kk++) {
            float a[8], b[8];
            #pragma unroll
            for (int i = 0; i < 4; i++) {
                a[i]   = Xs[kk][ty*4 + i];
                a[i+4] = Xs[kk][64 + ty*4 + i];
                b[i]   = Ws[kk][tx*4 + i];
                b[i+4] = Ws[kk][64 + tx*4 + i];
            }
            #pragma unroll
            for (int i = 0; i < 8; i++)
                #pragma unroll
                for (int j = 0; j < 8; j++)
                    acc[i][j] += a[i] * b[j];
        }
        __syncthreads();
    }

    #pragma unroll
    for (int ii = 0; ii < 8; ii++) {
        int rl = ty*4 + (ii & 3) + ((ii >> 2) << 6);
        int gr = bm + rl;
        #pragma unroll
        for (int jg = 0; jg < 2; jg++) {
            int col = bn + tx*4 + (jg << 6);
            float4 o;
            o.x = acc[ii][jg*4+0] + bo[col+0];
            o.y = acc[ii][jg*4+1] + bo[col+1];
            o.z = acc[ii][jg*4+2] + bo[col+2];
            o.w = acc[ii][jg*4+3] + bo[col+3];
            *(float4*)(out + (size_t)gr*DD + col) = o;
        }
    }
}

// ---------------------------------------------------------------------------
// Input order (insertion order of reference setup_inputs dict):
// 0 query, 1 key, 2 value, 3 Wq, 4 bq, 5 Wk, 6 bk, 7 Wv, 8 bv, 9 Wo, 10 bo
// ---------------------------------------------------------------------------
extern "C" void kernel_launch(void* const* d_in, const int* in_sizes, int n_in,
                              void* d_out, int out_size)
{
    (void)in_sizes; (void)n_in; (void)out_size;
    const float* query = (const float*)d_in[0];
    const float* key_  = (const float*)d_in[1];
    const float* value = (const float*)d_in[2];
    const float* Wq = (const float*)d_in[3];
    const float* bq = (const float*)d_in[4];
    const float* Wk = (const float*)d_in[5];
    const float* bk = (const float*)d_in[6];
    const float* Wv = (const float*)d_in[7];
    const float* bv = (const float*)d_in[8];
    const float* Wo = (const float*)d_in[9];
    const float* bo = (const float*)d_in[10];
    float* out = (float*)d_out;

    cudaFuncSetAttribute(attn_kernel,
                         cudaFuncAttributeMaxDynamicSharedMemorySize, ATTN_SMEM_BYTES);

    qkv_proj_kernel<<<dim3(DD/128, MR/128, 3), 256>>>(query, key_, value,
                                                      Wq, Wk, Wv, bq, bk, bv);
    attn_kernel<<<dim3(SS/64, BB*HH), 256, ATTN_SMEM_BYTES>>>();
    out_proj_kernel<<<dim3(DD/128, MR/128), 256>>>(Wo, bo, out);
}

// round 3
// speedup vs baseline: 1.2561x; 1.2561x over previous
#include <cuda_runtime.h>
#include <cstdint>

#define BB 4
#define SS 2048
#define HH 16
#define DKK 64
#define DD 1024
#define MR (BB*SS)        // 8192 rows

// Scratch: Q,K,V,attn-out in [B,H,S,64] layout (device globals; no allocs)
__device__ float g_Q[(size_t)BB*HH*SS*DKK];
__device__ float g_K[(size_t)BB*HH*SS*DKK];
__device__ float g_V[(size_t)BB*HH*SS*DKK];
__device__ float g_A[(size_t)BB*HH*SS*DKK];

static __device__ __forceinline__ uint32_t f2tf32(float x) {
    uint32_t u;
    asm("cvt.rna.tf32.f32 %0, %1;" : "=r"(u) : "f"(x));
    return u;
}

static __device__ __forceinline__ void mma_tf32(float c[4],
                                                const uint32_t a[4],
                                                const uint32_t b[2]) {
    asm volatile(
        "mma.sync.aligned.m16n8k8.row.col.f32.tf32.tf32.f32 "
        "{%0,%1,%2,%3}, {%4,%5,%6,%7}, {%8,%9}, {%0,%1,%2,%3};"
        : "+f"(c[0]), "+f"(c[1]), "+f"(c[2]), "+f"(c[3])
        : "r"(a[0]), "r"(a[1]), "r"(a[2]), "r"(a[3]), "r"(b[0]), "r"(b[1]));
}

// ---------------------------------------------------------------------------
// mma.sync tf32 GEMM:  C[128x128 tile] = A @ B^T (+bias)
// MODE 0: A = X (row-major [8192,1024]); blockIdx.z selects Q/K/V; out -> [B,H,S,64]
// MODE 1: A = gather from g_A; out linear [B,S,D]
// 256 threads = 8 warps in 2(M) x 4(N); warp tile 64x32; BK=16 (2 k-steps of 8).
// Double-buffered smem, pitch 20 (conflict-free quad access).
// ---------------------------------------------------------------------------
#define NCHUNK (DD/16)   // 64

template<int MODE>
__global__ __launch_bounds__(256, 1) void mma_gemm(
    const float* __restrict__ X0, const float* __restrict__ X1, const float* __restrict__ X2,
    const float* __restrict__ W0, const float* __restrict__ W1, const float* __restrict__ W2,
    const float* __restrict__ b0, const float* __restrict__ b1, const float* __restrict__ b2,
    float* __restrict__ outp)
{
    __shared__ uint32_t As[2][128][20];
    __shared__ uint32_t Bs[2][128][20];

    const int tid  = threadIdx.x;
    const int wid  = tid >> 5, lane = tid & 31;
    const int wm   = wid >> 2, wn = wid & 3;          // warp 64x32 tile at (wm*64, wn*32)
    const int bm   = blockIdx.y * 128, bn = blockIdx.x * 128;
    const int qr   = lane >> 2, qc = lane & 3;        // quad row/col

    const float *Asrc, *W, *bias; float* out;
    if (MODE == 0) {
        int z = blockIdx.z;
        Asrc = (z == 0) ? X0 : (z == 1) ? X1 : X2;
        W    = (z == 0) ? W0 : (z == 1) ? W1 : W2;
        bias = (z == 0) ? b0 : (z == 1) ? b1 : b2;
        out  = (z == 0) ? g_Q : (z == 1) ? g_K : g_V;
    } else {
        Asrc = g_A; W = W0; bias = b0; out = outp;
    }

    // staging mapping: thread -> row (0..127), 8 cols starting at c8
    const int srow = tid >> 1;
    const int c8   = (tid & 1) * 8;

    float4 fa0, fa1, fb0, fb1;
    #define LOAD_REG(chunk) do { \
        int k0 = (chunk) * 16; \
        const float* ap; \
        if (MODE == 0) { \
            ap = Asrc + (size_t)(bm + srow) * DD + k0 + c8; \
        } else { \
            int gr = bm + srow; int b_ = gr >> 11; int s_ = gr & 2047; \
            int h_ = k0 >> 6;  int d0 = (k0 & 63) + c8; \
            ap = Asrc + (((size_t)(b_ * HH + h_) * SS + s_) * DKK + d0); \
        } \
        fa0 = *(const float4*)(ap); \
        fa1 = *(const float4*)(ap + 4); \
        const float* bp = W + (size_t)(bn + srow) * DD + k0 + c8; \
        fb0 = *(const float4*)(bp); \
        fb1 = *(const float4*)(bp + 4); \
    } while (0)

    #define STS(s) do { \
        uint4 ua0 = make_uint4(f2tf32(fa0.x), f2tf32(fa0.y), f2tf32(fa0.z), f2tf32(fa0.w)); \
        uint4 ua1 = make_uint4(f2tf32(fa1.x), f2tf32(fa1.y), f2tf32(fa1.z), f2tf32(fa1.w)); \
        uint4 ub0 = make_uint4(f2tf32(fb0.x), f2tf32(fb0.y), f2tf32(fb0.z), f2tf32(fb0.w)); \
        uint4 ub1 = make_uint4(f2tf32(fb1.x), f2tf32(fb1.y), f2tf32(fb1.z), f2tf32(fb1.w)); \
        *(uint4*)&As[s][srow][c8]     = ua0; \
        *(uint4*)&As[s][srow][c8 + 4] = ua1; \
        *(uint4*)&Bs[s][srow][c8]     = ub0; \
        *(uint4*)&Bs[s][srow][c8 + 4] = ub1; \
    } while (0)

    float acc[4][4][4];
    #pragma unroll
    for (int i = 0; i < 4; i++)
        #pragma unroll
        for (int j = 0; j < 4; j++)
            #pragma unroll
            for (int k = 0; k < 4; k++) acc[i][j][k] = 0.f;

    LOAD_REG(0);

    for (int i = 0; i < NCHUNK; i++) {
        int s = i & 1;
        STS(s);
        __syncthreads();
        if (i + 1 < NCHUNK) LOAD_REG(i + 1);
        #pragma unroll
        for (int ks = 0; ks < 2; ks++) {
            int k8 = ks * 8;
            uint32_t af[4][4], bf[4][2];
            #pragma unroll
            for (int mi = 0; mi < 4; mi++) {
                int r = wm * 64 + mi * 16 + qr;
                af[mi][0] = As[s][r][k8 + qc];
                af[mi][1] = As[s][r + 8][k8 + qc];
                af[mi][2] = As[s][r][k8 + 4 + qc];
                af[mi][3] = As[s][r + 8][k8 + 4 + qc];
            }
            #pragma unroll
            for (int ni = 0; ni < 4; ni++) {
                int nr = wn * 32 + ni * 8 + qr;
                bf[ni][0] = Bs[s][nr][k8 + qc];
                bf[ni][1] = Bs[s][nr][k8 + 4 + qc];
            }
            #pragma unroll
            for (int mi = 0; mi < 4; mi++)
                #pragma unroll
                for (int ni = 0; ni < 4; ni++)
                    mma_tf32(acc[mi][ni], af[mi], bf[ni]);
        }
        __syncthreads();
    }

    // epilogue: acc frag (mi,ni): rows r, r+8; cols 2*qc, 2*qc+1 within 16x8 tile
    #pragma unroll
    for (int mi = 0; mi < 4; mi++) {
        #pragma unroll
        for (int half = 0; half < 2; half++) {
            int gr = bm + wm * 64 + mi * 16 + qr + half * 8;
            #pragma unroll
            for (int ni = 0; ni < 4; ni++) {
                int cn = bn + wn * 32 + ni * 8 + 2 * qc;
                float v0 = acc[mi][ni][half * 2 + 0] + bias[cn];
                float v1 = acc[mi][ni][half * 2 + 1] + bias[cn + 1];
                if (MODE == 0) {
                    int b_ = gr >> 11, s_ = gr & 2047;
                    int h_ = cn >> 6,  d_ = cn & 63;
                    float2* p = (float2*)(out + (((size_t)(b_ * HH + h_) * SS + s_) * DKK + d_));
                    *p = make_float2(v0, v1);
                } else {
                    float2* p = (float2*)(out + (size_t)gr * DD + cn);
                    *p = make_float2(v0, v1);
                }
            }
        }
    }
}

// ---------------------------------------------------------------------------
// Kernel 2: flash-style attention per (b,h).  BM=64 queries, BN=64 keys/iter.
// 256 threads (16x16), 4x4 per thread. Online softmax, O = softmax(QK^T/8)V.
// ---------------------------------------------------------------------------
#define ATTN_SMEM_FLOATS (4*64*68 + 192)
#define ATTN_SMEM_BYTES  (ATTN_SMEM_FLOATS * 4)

__global__ __launch_bounds__(256) void attn_kernel()
{
    extern __shared__ float sm[];
    float (*Qt)[68] = (float(*)[68])sm;               // [k][qrow]   transposed
    float (*Kt)[68] = (float(*)[68])(sm + 64*68);     // [k][krow]   transposed
    float (*Vs)[68] = (float(*)[68])(sm + 2*64*68);   // [krow][d]
    float (*Ps)[68] = (float(*)[68])(sm + 3*64*68);   // [qrow][krow]
    float* m_s = sm + 4*64*68;
    float* l_s = m_s + 64;
    float* f_s = m_s + 128;

    const int tid = threadIdx.x;
    const int tx = tid & 15, ty = tid >> 4;
    const int bh = blockIdx.y;
    const int q0 = blockIdx.x * 64;
    const float* Qp = g_Q + (size_t)bh * SS * DKK;
    const float* Kp = g_K + (size_t)bh * SS * DKK;
    const float* Vp = g_V + (size_t)bh * SS * DKK;
    float* Ap = g_A + (size_t)bh * SS * DKK;

    if (tid < 64) { m_s[tid] = -1e30f; l_s[tid] = 0.f; }

    #pragma unroll
    for (int ii = 0; ii < 4; ii++) {
        int f = tid + 256*ii;
        int r = f >> 4, c = (f & 15) << 2;
        float4 v = *(const float4*)(Qp + (size_t)(q0 + r)*DKK + c);
        Qt[c+0][r] = v.x; Qt[c+1][r] = v.y; Qt[c+2][r] = v.z; Qt[c+3][r] = v.w;
    }
    __syncthreads();

    float acc[4][4];
    #pragma unroll
    for (int i = 0; i < 4; i++)
        #pragma unroll
        for (int j = 0; j < 4; j++) acc[i][j] = 0.f;

    for (int kb = 0; kb < SS/64; kb++) {
        const float* Kb = Kp + (size_t)kb*64*DKK;
        const float* Vb = Vp + (size_t)kb*64*DKK;
        #pragma unroll
        for (int ii = 0; ii < 4; ii++) {
            int f = tid + 256*ii;
            int r = f >> 4, c = (f & 15) << 2;
            float4 kv = *(const float4*)(Kb + (size_t)r*DKK + c);
            Kt[c+0][r] = kv.x; Kt[c+1][r] = kv.y; Kt[c+2][r] = kv.z; Kt[c+3][r] = kv.w;
            *(float4*)&Vs[r][c] = *(const float4*)(Vb + (size_t)r*DKK + c);
        }
        __syncthreads();

        float s[4][4];
        #pragma unroll
        for (int i = 0; i < 4; i++)
            #pragma unroll
            for (int j = 0; j < 4; j++) s[i][j] = 0.f;

        #pragma unroll 8
        for (int k = 0; k < 64; k++) {
            float4 aa = *(const float4*)&Qt[k][ty*4];
            float4 bb = *(const float4*)&Kt[k][tx*4];
            float a_[4] = {aa.x, aa.y, aa.z, aa.w};
            float b_[4] = {bb.x, bb.y, bb.z, bb.w};
            #pragma unroll
            for (int i = 0; i < 4; i++)
                #pragma unroll
                for (int j = 0; j < 4; j++)
                    s[i][j] += a_[i] * b_[j];
        }
        #pragma unroll
        for (int i = 0; i < 4; i++) {
            float4 o = make_float4(s[i][0]*0.125f, s[i][1]*0.125f,
                                   s[i][2]*0.125f, s[i][3]*0.125f);
            *(float4*)&Ps[ty*4+i][tx*4] = o;
        }
        __syncthreads();

        if (tid < 64) {
            int r = tid;
            float mo = m_s[r];
            float mx = mo;
            #pragma unroll 8
            for (int j = 0; j < 64; j++) mx = fmaxf(mx, Ps[r][j]);
            float fac = __expf(mo - mx);
            float sum = 0.f;
            #pragma unroll 8
            for (int j = 0; j < 64; j++) {
                float p = __expf(Ps[r][j] - mx);
                Ps[r][j] = p;
                sum += p;
            }
            m_s[r] = mx;
            l_s[r] = l_s[r]*fac + sum;
            f_s[r] = fac;
        }
        __syncthreads();

        float fi[4];
        #pragma unroll
        for (int i = 0; i < 4; i++) fi[i] = f_s[ty*4+i];
        #pragma unroll
        for (int i = 0; i < 4; i++)
            #pragma unroll
            for (int j = 0; j < 4; j++) acc[i][j] *= fi[i];

        #pragma unroll 8
        for (int j = 0; j < 64; j++) {
            float4 vv = *(const float4*)&Vs[j][tx*4];
            float p0 = Ps[ty*4+0][j];
            float p1 = Ps[ty*4+1][j];
            float p2 = Ps[ty*4+2][j];
            float p3 = Ps[ty*4+3][j];
            acc[0][0] += p0*vv.x; acc[0][1] += p0*vv.y; acc[0][2] += p0*vv.z; acc[0][3] += p0*vv.w;
            acc[1][0] += p1*vv.x; acc[1][1] += p1*vv.y; acc[1][2] += p1*vv.z; acc[1][3] += p1*vv.w;
            acc[2][0] += p2*vv.x; acc[2][1] += p2*vv.y; acc[2][2] += p2*vv.z; acc[2][3] += p2*vv.w;
            acc[3][0] += p3*vv.x; acc[3][1] += p3*vv.y; acc[3][2] += p3*vv.z; acc[3][3] += p3*vv.w;
        }
        __syncthreads();
    }

    #pragma unroll
    for (int i = 0; i < 4; i++) {
        float inv = 1.f / l_s[ty*4+i];
        float4 o = make_float4(acc[i][0]*inv, acc[i][1]*inv, acc[i][2]*inv, acc[i][3]*inv);
        *(float4*)(Ap + (size_t)(q0 + ty*4+i)*DKK + tx*4) = o;
    }
}

// ---------------------------------------------------------------------------
// Input order: 0 query, 1 key, 2 value, 3 Wq, 4 bq, 5 Wk, 6 bk, 7 Wv, 8 bv, 9 Wo, 10 bo
// ---------------------------------------------------------------------------
extern "C" void kernel_launch(void* const* d_in, const int* in_sizes, int n_in,
                              void* d_out, int out_size)
{
    (void)in_sizes; (void)n_in; (void)out_size;
    const float* query = (const float*)d_in[0];
    const float* key_  = (const float*)d_in[1];
    const float* value = (const float*)d_in[2];
    const float* Wq = (const float*)d_in[3];
    const float* bq = (const float*)d_in[4];
    const float* Wk = (const float*)d_in[5];
    const float* bk = (const float*)d_in[6];
    const float* Wv = (const float*)d_in[7];
    const float* bv = (const float*)d_in[8];
    const float* Wo = (const float*)d_in[9];
    const float* bo = (const float*)d_in[10];
    float* out = (float*)d_out;

    cudaFuncSetAttribute(attn_kernel, cudaFuncAttributeMaxDynamicSharedMemorySize, ATTN_SMEM_BYTES);

    mma_gemm<0><<<dim3(DD/128, MR/128, 3), 256>>>(query, key_, value,
                                                  Wq, Wk, Wv, bq, bk, bv, nullptr);
    attn_kernel<<<dim3(SS/64, BB*HH), 256, ATTN_SMEM_BYTES>>>();
    mma_gemm<1><<<dim3(DD/128, MR/128, 1), 256>>>(nullptr, nullptr, nullptr,
                                                  Wo, nullptr, nullptr,
                                                  bo, nullptr, nullptr, out);
}

// round 4
// speedup vs baseline: 2.2210x; 1.7682x over previous
#include <cuda_runtime.h>
#include <cstdint>

#define BB 4
#define SS 2048
#define HH 16
#define DKK 64
#define DD 1024
#define MR (BB*SS)        // 8192 rows

// Scratch: Q,K,V,attn-out in [B,H,S,64] layout (device globals; no allocs)
__device__ float g_Q[(size_t)BB*HH*SS*DKK];
__device__ float g_K[(size_t)BB*HH*SS*DKK];
__device__ float g_V[(size_t)BB*HH*SS*DKK];
__device__ float g_A[(size_t)BB*HH*SS*DKK];

static __device__ __forceinline__ uint32_t f2tf32(float x) {
    uint32_t u;
    asm("cvt.rna.tf32.f32 %0, %1;" : "=r"(u) : "f"(x));
    return u;
}

static __device__ __forceinline__ void mma_tf32(float c[4],
                                                const uint32_t a[4],
                                                const uint32_t b[2]) {
    asm volatile(
        "mma.sync.aligned.m16n8k8.row.col.f32.tf32.tf32.f32 "
        "{%0,%1,%2,%3}, {%4,%5,%6,%7}, {%8,%9}, {%0,%1,%2,%3};"
        : "+f"(c[0]), "+f"(c[1]), "+f"(c[2]), "+f"(c[3])
        : "r"(a[0]), "r"(a[1]), "r"(a[2]), "r"(a[3]), "r"(b[0]), "r"(b[1]));
}

// ---------------------------------------------------------------------------
// mma.sync tf32 GEMM:  C[128x128 tile] = A @ B^T (+bias)   (unchanged from R3)
// ---------------------------------------------------------------------------
#define NCHUNK (DD/16)   // 64

template<int MODE>
__global__ __launch_bounds__(256, 1) void mma_gemm(
    const float* __restrict__ X0, const float* __restrict__ X1, const float* __restrict__ X2,
    const float* __restrict__ W0, const float* __restrict__ W1, const float* __restrict__ W2,
    const float* __restrict__ b0, const float* __restrict__ b1, const float* __restrict__ b2,
    float* __restrict__ outp)
{
    __shared__ uint32_t As[2][128][20];
    __shared__ uint32_t Bs[2][128][20];

    const int tid  = threadIdx.x;
    const int wid  = tid >> 5, lane = tid & 31;
    const int wm   = wid >> 2, wn = wid & 3;
    const int bm   = blockIdx.y * 128, bn = blockIdx.x * 128;
    const int qr   = lane >> 2, qc = lane & 3;

    const float *Asrc, *W, *bias; float* out;
    if (MODE == 0) {
        int z = blockIdx.z;
        Asrc = (z == 0) ? X0 : (z == 1) ? X1 : X2;
        W    = (z == 0) ? W0 : (z == 1) ? W1 : W2;
        bias = (z == 0) ? b0 : (z == 1) ? b1 : b2;
        out  = (z == 0) ? g_Q : (z == 1) ? g_K : g_V;
    } else {
        Asrc = g_A; W = W0; bias = b0; out = outp;
    }

    const int srow = tid >> 1;
    const int c8   = (tid & 1) * 8;

    float4 fa0, fa1, fb0, fb1;
    #define LOAD_REG(chunk) do { \
        int k0 = (chunk) * 16; \
        const float* ap; \
        if (MODE == 0) { \
            ap = Asrc + (size_t)(bm + srow) * DD + k0 + c8; \
        } else { \
            int gr = bm + srow; int b_ = gr >> 11; int s_ = gr & 2047; \
            int h_ = k0 >> 6;  int d0 = (k0 & 63) + c8; \
            ap = Asrc + (((size_t)(b_ * HH + h_) * SS + s_) * DKK + d0); \
        } \
        fa0 = *(const float4*)(ap); \
        fa1 = *(const float4*)(ap + 4); \
        const float* bp = W + (size_t)(bn + srow) * DD + k0 + c8; \
        fb0 = *(const float4*)(bp); \
        fb1 = *(const float4*)(bp + 4); \
    } while (0)

    #define STS(s) do { \
        uint4 ua0 = make_uint4(f2tf32(fa0.x), f2tf32(fa0.y), f2tf32(fa0.z), f2tf32(fa0.w)); \
        uint4 ua1 = make_uint4(f2tf32(fa1.x), f2tf32(fa1.y), f2tf32(fa1.z), f2tf32(fa1.w)); \
        uint4 ub0 = make_uint4(f2tf32(fb0.x), f2tf32(fb0.y), f2tf32(fb0.z), f2tf32(fb0.w)); \
        uint4 ub1 = make_uint4(f2tf32(fb1.x), f2tf32(fb1.y), f2tf32(fb1.z), f2tf32(fb1.w)); \
        *(uint4*)&As[s][srow][c8]     = ua0; \
        *(uint4*)&As[s][srow][c8 + 4] = ua1; \
        *(uint4*)&Bs[s][srow][c8]     = ub0; \
        *(uint4*)&Bs[s][srow][c8 + 4] = ub1; \
    } while (0)

    float acc[4][4][4];
    #pragma unroll
    for (int i = 0; i < 4; i++)
        #pragma unroll
        for (int j = 0; j < 4; j++)
            #pragma unroll
            for (int k = 0; k < 4; k++) acc[i][j][k] = 0.f;

    LOAD_REG(0);

    for (int i = 0; i < NCHUNK; i++) {
        int s = i & 1;
        STS(s);
        __syncthreads();
        if (i + 1 < NCHUNK) LOAD_REG(i + 1);
        #pragma unroll
        for (int ks = 0; ks < 2; ks++) {
            int k8 = ks * 8;
            uint32_t af[4][4], bf[4][2];
            #pragma unroll
            for (int mi = 0; mi < 4; mi++) {
                int r = wm * 64 + mi * 16 + qr;
                af[mi][0] = As[s][r][k8 + qc];
                af[mi][1] = As[s][r + 8][k8 + qc];
                af[mi][2] = As[s][r][k8 + 4 + qc];
                af[mi][3] = As[s][r + 8][k8 + 4 + qc];
            }
            #pragma unroll
            for (int ni = 0; ni < 4; ni++) {
                int nr = wn * 32 + ni * 8 + qr;
                bf[ni][0] = Bs[s][nr][k8 + qc];
                bf[ni][1] = Bs[s][nr][k8 + 4 + qc];
            }
            #pragma unroll
            for (int mi = 0; mi < 4; mi++)
                #pragma unroll
                for (int ni = 0; ni < 4; ni++)
                    mma_tf32(acc[mi][ni], af[mi], bf[ni]);
        }
        __syncthreads();
    }

    #pragma unroll
    for (int mi = 0; mi < 4; mi++) {
        #pragma unroll
        for (int half = 0; half < 2; half++) {
            int gr = bm + wm * 64 + mi * 16 + qr + half * 8;
            #pragma unroll
            for (int ni = 0; ni < 4; ni++) {
                int cn = bn + wn * 32 + ni * 8 + 2 * qc;
                float v0 = acc[mi][ni][half * 2 + 0] + bias[cn];
                float v1 = acc[mi][ni][half * 2 + 1] + bias[cn + 1];
                if (MODE == 0) {
                    int b_ = gr >> 11, s_ = gr & 2047;
                    int h_ = cn >> 6,  d_ = cn & 63;
                    float2* p = (float2*)(out + (((size_t)(b_ * HH + h_) * SS + s_) * DKK + d_));
                    *p = make_float2(v0, v1);
                } else {
                    float2* p = (float2*)(out + (size_t)gr * DD + cn);
                    *p = make_float2(v0, v1);
                }
            }
        }
    }
}

// ---------------------------------------------------------------------------
// Attention with mma.sync tf32.  Block = 128 q rows of one (b,h).
// 8 warps x 16 q-rows. 64-key tiles. Q frags in regs (pre-scaled by 1/8).
// Register online softmax; P->A-frag relayout via intra-quad shuffles.
// ---------------------------------------------------------------------------
#define ATP 68

__global__ __launch_bounds__(256, 1) void attn_mma()
{
    __shared__ uint32_t Ks[64][ATP];
    __shared__ uint32_t Vs[64][ATP];

    const int tid  = threadIdx.x;
    const int wid  = tid >> 5, lane = tid & 31;
    const int qr   = lane >> 2, qc = lane & 3;
    const int bh   = blockIdx.y;
    const int q0   = blockIdx.x * 128;
    const int w16  = wid * 16;

    const float* Qp = g_Q + (size_t)bh * SS * DKK;
    const float* Kp = g_K + (size_t)bh * SS * DKK;
    const float* Vp = g_V + (size_t)bh * SS * DKK;
    float*       Ap = g_A + (size_t)bh * SS * DKK;

    // Q fragments (scaled by 1/8), kept in registers for the whole kernel
    uint32_t qf[8][4];
    {
        const float* Qr0 = Qp + (size_t)(q0 + w16 + qr) * DKK;
        const float* Qr1 = Qr0 + 8 * DKK;
        #pragma unroll
        for (int ks = 0; ks < 8; ks++) {
            int c = ks * 8 + qc;
            qf[ks][0] = f2tf32(Qr0[c]     * 0.125f);
            qf[ks][1] = f2tf32(Qr1[c]     * 0.125f);
            qf[ks][2] = f2tf32(Qr0[c + 4] * 0.125f);
            qf[ks][3] = f2tf32(Qr1[c + 4] * 0.125f);
        }
    }

    float m0 = -1e30f, m1 = -1e30f, l0 = 0.f, l1 = 0.f;
    float o[8][4];
    #pragma unroll
    for (int i = 0; i < 8; i++)
        #pragma unroll
        for (int j = 0; j < 4; j++) o[i][j] = 0.f;

    // staging map: row = tid>>2 (0..63), 16-col group = (tid&3)*16
    const int sr = tid >> 2;
    const int sc16 = (tid & 3) * 16;

    const int src0 = (lane & 28) | (qc >> 1);   // quad-local source lanes
    const int src2 = src0 + 2;
    const int e = qc & 1;

    for (int kb = 0; kb < SS / 64; kb++) {
        const float* Kb = Kp + (size_t)kb * 64 * DKK;
        const float* Vb = Vp + (size_t)kb * 64 * DKK;
        #pragma unroll
        for (int j = 0; j < 4; j++) {
            int c = sc16 + j * 4;
            float4 kv = *(const float4*)(Kb + (size_t)sr * DKK + c);
            float4 vv = *(const float4*)(Vb + (size_t)sr * DKK + c);
            Ks[sr][c+0] = f2tf32(kv.x); Ks[sr][c+1] = f2tf32(kv.y);
            Ks[sr][c+2] = f2tf32(kv.z); Ks[sr][c+3] = f2tf32(kv.w);
            Vs[sr][c+0] = f2tf32(vv.x); Vs[sr][c+1] = f2tf32(vv.y);
            Vs[sr][c+2] = f2tf32(vv.z); Vs[sr][c+3] = f2tf32(vv.w);
        }
        __syncthreads();

        // S = (Q/8) K^T : sc[ni] covers cols ni*8..ni*8+7
        float sc[8][4];
        #pragma unroll
        for (int i = 0; i < 8; i++)
            #pragma unroll
            for (int j = 0; j < 4; j++) sc[i][j] = 0.f;

        #pragma unroll
        for (int ks = 0; ks < 8; ks++) {
            #pragma unroll
            for (int ni = 0; ni < 8; ni++) {
                uint32_t b[2];
                b[0] = Ks[ni * 8 + qr][ks * 8 + qc];
                b[1] = Ks[ni * 8 + qr][ks * 8 + qc + 4];
                mma_tf32(sc[ni], qf[ks], b);
            }
        }

        // online softmax (rows qr -> m0/l0, qr+8 -> m1/l1)
        float mx0 = -1e30f, mx1 = -1e30f;
        #pragma unroll
        for (int ni = 0; ni < 8; ni++) {
            mx0 = fmaxf(mx0, fmaxf(sc[ni][0], sc[ni][1]));
            mx1 = fmaxf(mx1, fmaxf(sc[ni][2], sc[ni][3]));
        }
        mx0 = fmaxf(mx0, __shfl_xor_sync(0xffffffffu, mx0, 1));
        mx0 = fmaxf(mx0, __shfl_xor_sync(0xffffffffu, mx0, 2));
        mx1 = fmaxf(mx1, __shfl_xor_sync(0xffffffffu, mx1, 1));
        mx1 = fmaxf(mx1, __shfl_xor_sync(0xffffffffu, mx1, 2));
        float mn0 = fmaxf(m0, mx0), mn1 = fmaxf(m1, mx1);
        float fac0 = __expf(m0 - mn0), fac1 = __expf(m1 - mn1);
        float rs0 = 0.f, rs1 = 0.f;
        #pragma unroll
        for (int ni = 0; ni < 8; ni++) {
            sc[ni][0] = __expf(sc[ni][0] - mn0);
            sc[ni][1] = __expf(sc[ni][1] - mn0);
            sc[ni][2] = __expf(sc[ni][2] - mn1);
            sc[ni][3] = __expf(sc[ni][3] - mn1);
            rs0 += sc[ni][0] + sc[ni][1];
            rs1 += sc[ni][2] + sc[ni][3];
        }
        rs0 += __shfl_xor_sync(0xffffffffu, rs0, 1);
        rs0 += __shfl_xor_sync(0xffffffffu, rs0, 2);
        rs1 += __shfl_xor_sync(0xffffffffu, rs1, 1);
        rs1 += __shfl_xor_sync(0xffffffffu, rs1, 2);
        l0 = l0 * fac0 + rs0;  m0 = mn0;
        l1 = l1 * fac1 + rs1;  m1 = mn1;
        #pragma unroll
        for (int ni = 0; ni < 8; ni++) {
            o[ni][0] *= fac0; o[ni][1] *= fac0;
            o[ni][2] *= fac1; o[ni][3] *= fac1;
        }

        // O += P V.  A-frag of P for k-step ks comes from score frag sc[ks]
        // via intra-quad shuffle relayout.
        #pragma unroll
        for (int ks = 0; ks < 8; ks++) {
            float x0 = __shfl_sync(0xffffffffu, sc[ks][0], src0);
            float x1 = __shfl_sync(0xffffffffu, sc[ks][1], src0);
            float y0 = __shfl_sync(0xffffffffu, sc[ks][2], src0);
            float y1 = __shfl_sync(0xffffffffu, sc[ks][3], src0);
            float z0 = __shfl_sync(0xffffffffu, sc[ks][0], src2);
            float z1 = __shfl_sync(0xffffffffu, sc[ks][1], src2);
            float w0 = __shfl_sync(0xffffffffu, sc[ks][2], src2);
            float w1 = __shfl_sync(0xffffffffu, sc[ks][3], src2);
            uint32_t a[4];
            a[0] = f2tf32(e ? x1 : x0);
            a[1] = f2tf32(e ? y1 : y0);
            a[2] = f2tf32(e ? z1 : z0);
            a[3] = f2tf32(e ? w1 : w0);
            #pragma unroll
            for (int ni = 0; ni < 8; ni++) {
                uint32_t b[2];
                b[0] = Vs[ks * 8 + qc][ni * 8 + qr];
                b[1] = Vs[ks * 8 + qc + 4][ni * 8 + qr];
                mma_tf32(o[ni], a, b);
            }
        }
        __syncthreads();
    }

    float inv0 = 1.f / l0, inv1 = 1.f / l1;
    float* Or0 = Ap + (size_t)(q0 + w16 + qr) * DKK;
    float* Or1 = Or0 + 8 * DKK;
    #pragma unroll
    for (int ni = 0; ni < 8; ni++) {
        int c = ni * 8 + 2 * qc;
        *(float2*)(Or0 + c) = make_float2(o[ni][0] * inv0, o[ni][1] * inv0);
        *(float2*)(Or1 + c) = make_float2(o[ni][2] * inv1, o[ni][3] * inv1);
    }
}

// ---------------------------------------------------------------------------
// Input order: 0 query, 1 key, 2 value, 3 Wq, 4 bq, 5 Wk, 6 bk, 7 Wv, 8 bv, 9 Wo, 10 bo
// ---------------------------------------------------------------------------
extern "C" void kernel_launch(void* const* d_in, const int* in_sizes, int n_in,
                              void* d_out, int out_size)
{
    (void)in_sizes; (void)n_in; (void)out_size;
    const float* query = (const float*)d_in[0];
    const float* key_  = (const float*)d_in[1];
    const float* value = (const float*)d_in[2];
    const float* Wq = (const float*)d_in[3];
    const float* bq = (const float*)d_in[4];
    const float* Wk = (const float*)d_in[5];
    const float* bk = (const float*)d_in[6];
    const float* Wv = (const float*)d_in[7];
    const float* bv = (const float*)d_in[8];
    const float* Wo = (const float*)d_in[9];
    const float* bo = (const float*)d_in[10];
    float* out = (float*)d_out;

    mma_gemm<0><<<dim3(DD/128, MR/128, 3), 256>>>(query, key_, value,
                                                  Wq, Wk, Wv, bq, bk, bv, nullptr);
    attn_mma<<<dim3(SS/128, BB*HH), 256>>>();
    mma_gemm<1><<<dim3(DD/128, MR/128, 1), 256>>>(nullptr, nullptr, nullptr,
                                                  Wo, nullptr, nullptr,
                                                  bo, nullptr, nullptr, out);
}

// round 5
// speedup vs baseline: 3.2363x; 1.4571x over previous
#include <cuda_runtime.h>
#include <cstdint>

#define BB 4
#define SS 2048
#define HH 16
#define DKK 64
#define DD 1024
#define MR (BB*SS)        // 8192 rows

// tf32-bit scratch (device globals; no allocs)
__device__ uint32_t g_Xq[(size_t)MR*DD];
__device__ uint32_t g_Xk[(size_t)MR*DD];
__device__ uint32_t g_Xv[(size_t)MR*DD];
__device__ uint32_t g_Wq[(size_t)DD*DD];
__device__ uint32_t g_Wk[(size_t)DD*DD];
__device__ uint32_t g_Wv[(size_t)DD*DD];
__device__ uint32_t g_Wo[(size_t)DD*DD];
__device__ uint32_t g_Q[(size_t)BB*HH*SS*DKK];
__device__ uint32_t g_K[(size_t)BB*HH*SS*DKK];
__device__ uint32_t g_V[(size_t)BB*HH*SS*DKK];
__device__ uint32_t g_A[(size_t)BB*HH*SS*DKK];

static __device__ __forceinline__ uint32_t f2tf32(float x) {
    uint32_t u;
    asm("cvt.rna.tf32.f32 %0, %1;" : "=r"(u) : "f"(x));
    return u;
}

static __device__ __forceinline__ void mma_tf32(float c[4],
                                                const uint32_t a[4],
                                                const uint32_t b[2]) {
    asm volatile(
        "mma.sync.aligned.m16n8k8.row.col.f32.tf32.tf32.f32 "
        "{%0,%1,%2,%3}, {%4,%5,%6,%7}, {%8,%9}, {%0,%1,%2,%3};"
        : "+f"(c[0]), "+f"(c[1]), "+f"(c[2]), "+f"(c[3])
        : "r"(a[0]), "r"(a[1]), "r"(a[2]), "r"(a[3]), "r"(b[0]), "r"(b[1]));
}

static __device__ __forceinline__ uint32_t smem_u32(const void* p) {
    uint32_t a;
    asm("{ .reg .u64 t; cvta.to.shared.u64 t, %1; cvt.u32.u64 %0, t; }" : "=r"(a) : "l"(p));
    return a;
}
static __device__ __forceinline__ void cpa16(uint32_t s, const void* g) {
    asm volatile("cp.async.cg.shared.global [%0], [%1], 16;" :: "r"(s), "l"(g) : "memory");
}
#define CPA_COMMIT() asm volatile("cp.async.commit_group;" ::: "memory")
#define CPA_WAIT2()  asm volatile("cp.async.wait_group 2;" ::: "memory")

static __device__ __forceinline__ void ldsm4(uint32_t d[4], uint32_t addr) {
    asm volatile("ldmatrix.sync.aligned.m8n8.x4.shared.b16 {%0,%1,%2,%3}, [%4];"
                 : "=r"(d[0]), "=r"(d[1]), "=r"(d[2]), "=r"(d[3]) : "r"(addr));
}

// ---------------------------------------------------------------------------
// elementwise fp32 -> tf32(RNA) bit conversion
// ---------------------------------------------------------------------------
template<int SEL>
__global__ void conv_tf32(const float4* __restrict__ src, int n4)
{
    uint32_t* dst = (SEL == 0) ? g_Xq : (SEL == 1) ? g_Xk : (SEL == 2) ? g_Xv :
                    (SEL == 3) ? g_Wq : (SEL == 4) ? g_Wk : (SEL == 5) ? g_Wv : g_Wo;
    int i = blockIdx.x * blockDim.x + threadIdx.x;
    if (i < n4) {
        float4 v = src[i];
        ((uint4*)dst)[i] = make_uint4(f2tf32(v.x), f2tf32(v.y), f2tf32(v.z), f2tf32(v.w));
    }
}

// ---------------------------------------------------------------------------
// tf32 GEMM: C[128x128] = A @ B^T (+bias).  cp.async 4-stage + ldmatrix.
// MODE 0: A = g_Xq/g_Xk/g_Xv (z), W = g_Wq/..., out tf32 -> g_Q/g_K/g_V
// MODE 1: A = gather(g_A), W = g_Wo, out fp32 -> d_out
// 256 threads = 8 warps (2M x 4N), warp tile 64x32, BK=16.
// smem tile: 128 rows x 64B, swizzle: kbyte ^= ((row>>1)&3)<<4.
// ---------------------------------------------------------------------------
#define NCHUNK (DD/16)   // 64
#define TILEB 8192
#define STGB  16384
#define GEMM_SMEM (4*STGB)   // 64 KB

template<int MODE>
__global__ __launch_bounds__(256, 2) void mma_gemm(
    const float* __restrict__ bq_, const float* __restrict__ bk_,
    const float* __restrict__ bv_, float* __restrict__ outp)
{
    extern __shared__ char smc[];
    uint32_t sbase = smem_u32(smc);

    const int tid  = threadIdx.x;
    const int wid  = tid >> 5, lane = tid & 31;
    const int wm   = wid >> 2, wn = wid & 3;
    const int bm   = blockIdx.y * 128, bn = blockIdx.x * 128;
    const int qr   = lane >> 2, qc = lane & 3;

    const uint32_t *Asrc, *W; const float* bias;
    if (MODE == 0) {
        int z = blockIdx.z;
        Asrc = (z == 0) ? g_Xq : (z == 1) ? g_Xk : g_Xv;
        W    = (z == 0) ? g_Wq : (z == 1) ? g_Wk : g_Wv;
        bias = (z == 0) ? bq_ : (z == 1) ? bk_ : bv_;
    } else {
        Asrc = g_A; W = g_Wo; bias = bq_;
    }

    // cp.async mapping: thread handles chunks {tid, tid+256}; chunk c -> (row c>>2, kb c&3)
    const int r0 = tid >> 2, kb = tid & 3;
    const int r1 = r0 + 64;
    const uint32_t dA0 = (uint32_t)(r0 * 64 + ((kb * 16) ^ (((r0 >> 1) & 3) << 4)));
    const uint32_t dA1 = (uint32_t)(r1 * 64 + ((kb * 16) ^ (((r1 >> 1) & 3) << 4)));

    // ldmatrix per-lane byte offsets (stage-local)
    const int g2 = lane >> 3, l7 = lane & 7;
    uint32_t offA[4][2], offB[2][2];
    #pragma unroll
    for (int mi = 0; mi < 4; mi++) {
        int row = wm * 64 + mi * 16 + (g2 & 1) * 8 + l7;
        int h = g2 >> 1;
        #pragma unroll
        for (int ks = 0; ks < 2; ks++)
            offA[mi][ks] = (uint32_t)(row * 64 + ((ks * 32 + h * 16) ^ (((row >> 1) & 3) << 4)));
    }
    #pragma unroll
    for (int p = 0; p < 2; p++) {
        int row = wn * 32 + p * 16 + (g2 >> 1) * 8 + l7;
        int h = g2 & 1;
        #pragma unroll
        for (int ks = 0; ks < 2; ks++)
            offB[p][ks] = (uint32_t)(TILEB + row * 64 + ((ks * 32 + h * 16) ^ (((row >> 1) & 3) << 4)));
    }

    #define ISSUE(chunk) do { \
        int k0_ = (chunk) * 16; \
        uint32_t sb_ = sbase + ((chunk) & 3) * STGB; \
        const uint32_t *a0_, *a1_; \
        if (MODE == 0) { \
            a0_ = Asrc + (size_t)(bm + r0) * DD + k0_ + kb * 4; \
            a1_ = Asrc + (size_t)(bm + r1) * DD + k0_ + kb * 4; \
        } else { \
            int h_ = k0_ >> 6, d_ = (k0_ & 63) + kb * 4; \
            int gr0_ = bm + r0, gr1_ = bm + r1; \
            a0_ = Asrc + (((size_t)((gr0_ >> 11) * HH + h_) * SS + (gr0_ & 2047)) * DKK + d_); \
            a1_ = Asrc + (((size_t)((gr1_ >> 11) * HH + h_) * SS + (gr1_ & 2047)) * DKK + d_); \
        } \
        cpa16(sb_ + dA0, a0_); \
        cpa16(sb_ + dA1, a1_); \
        cpa16(sb_ + TILEB + dA0, W + (size_t)(bn + r0) * DD + k0_ + kb * 4); \
        cpa16(sb_ + TILEB + dA1, W + (size_t)(bn + r1) * DD + k0_ + kb * 4); \
    } while (0)

    float acc[4][4][4];
    #pragma unroll
    for (int i = 0; i < 4; i++)
        #pragma unroll
        for (int j = 0; j < 4; j++)
            #pragma unroll
            for (int k = 0; k < 4; k++) acc[i][j][k] = 0.f;

    ISSUE(0); CPA_COMMIT();
    ISSUE(1); CPA_COMMIT();
    ISSUE(2); CPA_COMMIT();

    for (int i = 0; i < NCHUNK; i++) {
        CPA_WAIT2();
        __syncthreads();
        if (i + 3 < NCHUNK) ISSUE(i + 3);
        CPA_COMMIT();
        uint32_t base_ = sbase + (i & 3) * STGB;
        #pragma unroll
        for (int ks = 0; ks < 2; ks++) {
            uint32_t af[4][4], bqr[2][4];
            ldsm4(af[0], base_ + offA[0][ks]);
            ldsm4(af[1], base_ + offA[1][ks]);
            ldsm4(af[2], base_ + offA[2][ks]);
            ldsm4(af[3], base_ + offA[3][ks]);
            ldsm4(bqr[0], base_ + offB[0][ks]);
            ldsm4(bqr[1], base_ + offB[1][ks]);
            #pragma unroll
            for (int mi = 0; mi < 4; mi++)
                #pragma unroll
                for (int ni = 0; ni < 4; ni++)
                    mma_tf32(acc[mi][ni], af[mi], &bqr[ni >> 1][(ni & 1) * 2]);
        }
    }
    __syncthreads();

    // epilogue
    #pragma unroll
    for (int mi = 0; mi < 4; mi++) {
        #pragma unroll
        for (int half = 0; half < 2; half++) {
            int gr = bm + wm * 64 + mi * 16 + qr + half * 8;
            #pragma unroll
            for (int ni = 0; ni < 4; ni++) {
                int cn = bn + wn * 32 + ni * 8 + 2 * qc;
                float v0 = acc[mi][ni][half * 2 + 0] + bias[cn];
                float v1 = acc[mi][ni][half * 2 + 1] + bias[cn + 1];
                if (MODE == 0) {
                    uint32_t* out = (blockIdx.z == 0) ? g_Q : (blockIdx.z == 1) ? g_K : g_V;
                    int b_ = gr >> 11, s_ = gr & 2047;
                    int h_ = cn >> 6,  d_ = cn & 63;
                    uint2* p = (uint2*)(out + (((size_t)(b_ * HH + h_) * SS + s_) * DKK + d_));
                    *p = make_uint2(f2tf32(v0), f2tf32(v1));
                } else {
                    float2* p = (float2*)(outp + (size_t)gr * DD + cn);
                    *p = make_float2(v0, v1);
                }
            }
        }
    }
}

// ---------------------------------------------------------------------------
// Attention with mma.sync tf32 (operands already tf32 bits in g_Q/g_K/g_V).
// Block = 128 q rows of one (b,h); 8 warps x 16 q-rows; 64-key tiles.
// ---------------------------------------------------------------------------
#define ATP 68

__global__ __launch_bounds__(256, 1) void attn_mma()
{
    __shared__ uint32_t Ks[64][ATP];
    __shared__ uint32_t Vs[64][ATP];

    const int tid  = threadIdx.x;
    const int wid  = tid >> 5, lane = tid & 31;
    const int qr   = lane >> 2, qc = lane & 3;
    const int bh   = blockIdx.y;
    const int q0   = blockIdx.x * 128;
    const int w16  = wid * 16;

    const uint32_t* Qp = g_Q + (size_t)bh * SS * DKK;
    const uint32_t* Kp = g_K + (size_t)bh * SS * DKK;
    const uint32_t* Vp = g_V + (size_t)bh * SS * DKK;
    uint32_t*       Ap = g_A + (size_t)bh * SS * DKK;

    // Q fragments (scaled by 1/8 -- exact on tf32), in registers for whole kernel
    uint32_t qf[8][4];
    {
        const uint32_t* Qr0 = Qp + (size_t)(q0 + w16 + qr) * DKK;
        const uint32_t* Qr1 = Qr0 + 8 * DKK;
        #pragma unroll
        for (int ks = 0; ks < 8; ks++) {
            int c = ks * 8 + qc;
            qf[ks][0] = f2tf32(__uint_as_float(Qr0[c])     * 0.125f);
            qf[ks][1] = f2tf32(__uint_as_float(Qr1[c])     * 0.125f);
            qf[ks][2] = f2tf32(__uint_as_float(Qr0[c + 4]) * 0.125f);
            qf[ks][3] = f2tf32(__uint_as_float(Qr1[c + 4]) * 0.125f);
        }
    }

    float m0 = -1e30f, m1 = -1e30f, l0 = 0.f, l1 = 0.f;
    float o[8][4];
    #pragma unroll
    for (int i = 0; i < 8; i++)
        #pragma unroll
        for (int j = 0; j < 4; j++) o[i][j] = 0.f;

    const int sr = tid >> 2;
    const int sc16 = (tid & 3) * 16;

    const int src0 = (lane & 28) | (qc >> 1);
    const int src2 = src0 + 2;
    const int e = qc & 1;

    for (int kb = 0; kb < SS / 64; kb++) {
        const uint32_t* Kb = Kp + (size_t)kb * 64 * DKK;
        const uint32_t* Vb = Vp + (size_t)kb * 64 * DKK;
        #pragma unroll
        for (int j = 0; j < 4; j++) {
            int c = sc16 + j * 4;
            *(uint4*)&Ks[sr][c] = *(const uint4*)(Kb + (size_t)sr * DKK + c);
            *(uint4*)&Vs[sr][c] = *(const uint4*)(Vb + (size_t)sr * DKK + c);
        }
        __syncthreads();

        float sc[8][4];
        #pragma unroll
        for (int i = 0; i < 8; i++)
            #pragma unroll
            for (int j = 0; j < 4; j++) sc[i][j] = 0.f;

        #pragma unroll
        for (int ks = 0; ks < 8; ks++) {
            #pragma unroll
            for (int ni = 0; ni < 8; ni++) {
                uint32_t b[2];
                b[0] = Ks[ni * 8 + qr][ks * 8 + qc];
                b[1] = Ks[ni * 8 + qr][ks * 8 + qc + 4];
                mma_tf32(sc[ni], qf[ks], b);
            }
        }

        float mx0 = -1e30f, mx1 = -1e30f;
        #pragma unroll
        for (int ni = 0; ni < 8; ni++) {
            mx0 = fmaxf(mx0, fmaxf(sc[ni][0], sc[ni][1]));
            mx1 = fmaxf(mx1, fmaxf(sc[ni][2], sc[ni][3]));
        }
        mx0 = fmaxf(mx0, __shfl_xor_sync(0xffffffffu, mx0, 1));
        mx0 = fmaxf(mx0, __shfl_xor_sync(0xffffffffu, mx0, 2));
        mx1 = fmaxf(mx1, __shfl_xor_sync(0xffffffffu, mx1, 1));
        mx1 = fmaxf(mx1, __shfl_xor_sync(0xffffffffu, mx1, 2));
        float mn0 = fmaxf(m0, mx0), mn1 = fmaxf(m1, mx1);
        float fac0 = __expf(m0 - mn0), fac1 = __expf(m1 - mn1);
        float rs0 = 0.f, rs1 = 0.f;
        #pragma unroll
        for (int ni = 0; ni < 8; ni++) {
            sc[ni][0] = __expf(sc[ni][0] - mn0);
            sc[ni][1] = __expf(sc[ni][1] - mn0);
            sc[ni][2] = __expf(sc[ni][2] - mn1);
            sc[ni][3] = __expf(sc[ni][3] - mn1);
            rs0 += sc[ni][0] + sc[ni][1];
            rs1 += sc[ni][2] + sc[ni][3];
        }
        rs0 += __shfl_xor_sync(0xffffffffu, rs0, 1);
        rs0 += __shfl_xor_sync(0xffffffffu, rs0, 2);
        rs1 += __shfl_xor_sync(0xffffffffu, rs1, 1);
        rs1 += __shfl_xor_sync(0xffffffffu, rs1, 2);
        l0 = l0 * fac0 + rs0;  m0 = mn0;
        l1 = l1 * fac1 + rs1;  m1 = mn1;
        #pragma unroll
        for (int ni = 0; ni < 8; ni++) {
            o[ni][0] *= fac0; o[ni][1] *= fac0;
            o[ni][2] *= fac1; o[ni][3] *= fac1;
        }

        #pragma unroll
        for (int ks = 0; ks < 8; ks++) {
            float x0 = __shfl_sync(0xffffffffu, sc[ks][0], src0);
            float x1 = __shfl_sync(0xffffffffu, sc[ks][1], src0);
            float y0 = __shfl_sync(0xffffffffu, sc[ks][2], src0);
            float y1 = __shfl_sync(0xffffffffu, sc[ks][3], src0);
            float z0 = __shfl_sync(0xffffffffu, sc[ks][0], src2);
            float z1 = __shfl_sync(0xffffffffu, sc[ks][1], src2);
            float w0 = __shfl_sync(0xffffffffu, sc[ks][2], src2);
            float w1 = __shfl_sync(0xffffffffu, sc[ks][3], src2);
            uint32_t a[4];
            a[0] = f2tf32(e ? x1 : x0);
            a[1] = f2tf32(e ? y1 : y0);
            a[2] = f2tf32(e ? z1 : z0);
            a[3] = f2tf32(e ? w1 : w0);
            #pragma unroll
            for (int ni = 0; ni < 8; ni++) {
                uint32_t b[2];
                b[0] = Vs[ks * 8 + qc][ni * 8 + qr];
                b[1] = Vs[ks * 8 + qc + 4][ni * 8 + qr];
                mma_tf32(o[ni], a, b);
            }
        }
        __syncthreads();
    }

    float inv0 = 1.f / l0, inv1 = 1.f / l1;
    uint32_t* Or0 = Ap + (size_t)(q0 + w16 + qr) * DKK;
    uint32_t* Or1 = Or0 + 8 * DKK;
    #pragma unroll
    for (int ni = 0; ni < 8; ni++) {
        int c = ni * 8 + 2 * qc;
        *(uint2*)(Or0 + c) = make_uint2(f2tf32(o[ni][0] * inv0), f2tf32(o[ni][1] * inv0));
        *(uint2*)(Or1 + c) = make_uint2(f2tf32(o[ni][2] * inv1), f2tf32(o[ni][3] * inv1));
    }
}

// ---------------------------------------------------------------------------
// Input order: 0 query, 1 key, 2 value, 3 Wq, 4 bq, 5 Wk, 6 bk, 7 Wv, 8 bv, 9 Wo, 10 bo
// ---------------------------------------------------------------------------
extern "C" void kernel_launch(void* const* d_in, const int* in_sizes, int n_in,
                              void* d_out, int out_size)
{
    (void)in_sizes; (void)n_in; (void)out_size;
    const float* query = (const float*)d_in[0];
    const float* key_  = (const float*)d_in[1];
    const float* value = (const float*)d_in[2];
    const float* Wq = (const float*)d_in[3];
    const float* bq = (const float*)d_in[4];
    const float* Wk = (const float*)d_in[5];
    const float* bk = (const float*)d_in[6];
    const float* Wv = (const float*)d_in[7];
    const float* bv = (const float*)d_in[8];
    const float* Wo = (const float*)d_in[9];
    const float* bo = (const float*)d_in[10];
    float* out = (float*)d_out;

    cudaFuncSetAttribute(mma_gemm<0>, cudaFuncAttributeMaxDynamicSharedMemorySize, GEMM_SMEM);
    cudaFuncSetAttribute(mma_gemm<1>, cudaFuncAttributeMaxDynamicSharedMemorySize, GEMM_SMEM);

    const int NX4 = MR * DD / 4;     // 2097152
    const int NW4 = DD * DD / 4;     // 262144
    conv_tf32<0><<<NX4 / 256, 256>>>((const float4*)query, NX4);
    conv_tf32<1><<<NX4 / 256, 256>>>((const float4*)key_,  NX4);
    conv_tf32<2><<<NX4 / 256, 256>>>((const float4*)value, NX4);
    conv_tf32<3><<<NW4 / 256, 256>>>((const float4*)Wq, NW4);
    conv_tf32<4><<<NW4 / 256, 256>>>((const float4*)Wk, NW4);
    conv_tf32<5><<<NW4 / 256, 256>>>((const float4*)Wv, NW4);
    conv_tf32<6><<<NW4 / 256, 256>>>((const float4*)Wo, NW4);

    mma_gemm<0><<<dim3(DD/128, MR/128, 3), 256, GEMM_SMEM>>>(bq, bk, bv, nullptr);
    attn_mma<<<dim3(SS/128, BB*HH), 256>>>();
    mma_gemm<1><<<dim3(DD/128, MR/128, 1), 256, GEMM_SMEM>>>(bo, nullptr, nullptr, out);
}

// round 7
// speedup vs baseline: 3.5112x; 1.0849x over previous
#include <cuda_runtime.h>
#include <cstdint>

#define BB 4
#define SS 2048
#define HH 16
#define DKK 64
#define DD 1024
#define MR (BB*SS)        // 8192 rows

// tf32-bit scratch (device globals; no allocs)
__device__ uint32_t g_Xq[(size_t)MR*DD];
__device__ uint32_t g_Xk[(size_t)MR*DD];
__device__ uint32_t g_Xv[(size_t)MR*DD];
__device__ uint32_t g_Wq[(size_t)DD*DD];
__device__ uint32_t g_Wk[(size_t)DD*DD];
__device__ uint32_t g_Wv[(size_t)DD*DD];
__device__ uint32_t g_Wo[(size_t)DD*DD];
__device__ uint32_t g_Q[(size_t)BB*HH*SS*DKK];
__device__ uint32_t g_K[(size_t)BB*HH*SS*DKK];
__device__ uint32_t g_V[(size_t)BB*HH*SS*DKK];
__device__ uint32_t g_A[(size_t)BB*HH*SS*DKK];

static __device__ __forceinline__ uint32_t f2tf32(float x) {
    uint32_t u;
    asm("cvt.rna.tf32.f32 %0, %1;" : "=r"(u) : "f"(x));
    return u;
}

static __device__ __forceinline__ void mma_tf32(float c[4],
                                                const uint32_t a[4],
                                                const uint32_t b[2]) {
    asm volatile(
        "mma.sync.aligned.m16n8k8.row.col.f32.tf32.tf32.f32 "
        "{%0,%1,%2,%3}, {%4,%5,%6,%7}, {%8,%9}, {%0,%1,%2,%3};"
        : "+f"(c[0]), "+f"(c[1]), "+f"(c[2]), "+f"(c[3])
        : "r"(a[0]), "r"(a[1]), "r"(a[2]), "r"(a[3]), "r"(b[0]), "r"(b[1]));
}

static __device__ __forceinline__ uint32_t smem_u32(const void* p) {
    uint32_t a;
    asm("{ .reg .u64 t; cvta.to.shared.u64 t, %1; cvt.u32.u64 %0, t; }" : "=r"(a) : "l"(p));
    return a;
}
static __device__ __forceinline__ void cpa16(uint32_t s, const void* g) {
    asm volatile("cp.async.cg.shared.global [%0], [%1], 16;" :: "r"(s), "l"(g) : "memory");
}
#define CPA_COMMIT() asm volatile("cp.async.commit_group;" ::: "memory")
#define CPA_WAIT2()  asm volatile("cp.async.wait_group 2;" ::: "memory")
#define CPA_WAIT1()  asm volatile("cp.async.wait_group 1;" ::: "memory")
#define CPA_WAIT0()  asm volatile("cp.async.wait_group 0;" ::: "memory")

static __device__ __forceinline__ void ldsm4(uint32_t d[4], uint32_t addr) {
    asm volatile("ldmatrix.sync.aligned.m8n8.x4.shared.b16 {%0,%1,%2,%3}, [%4];"
                 : "=r"(d[0]), "=r"(d[1]), "=r"(d[2]), "=r"(d[3]) : "r"(addr));
}

// ---------------------------------------------------------------------------
// elementwise fp32 -> tf32(RNA) bit conversion, grid-stride ILP=4
// ---------------------------------------------------------------------------
template<int SEL>
__global__ void conv_tf32(const float4* __restrict__ src, int n4)
{
    uint32_t* dst = (SEL == 0) ? g_Xq : (SEL == 1) ? g_Xk : (SEL == 2) ? g_Xv :
                    (SEL == 3) ? g_Wq : (SEL == 4) ? g_Wk : (SEL == 5) ? g_Wv : g_Wo;
    int base = blockIdx.x * (blockDim.x * 4) + threadIdx.x;
    float4 v[4];
    #pragma unroll
    for (int j = 0; j < 4; j++) v[j] = src[base + j * 256];
    #pragma unroll
    for (int j = 0; j < 4; j++)
        ((uint4*)dst)[base + j * 256] =
            make_uint4(f2tf32(v[j].x), f2tf32(v[j].y), f2tf32(v[j].z), f2tf32(v[j].w));
}

// ---------------------------------------------------------------------------
// tf32 GEMM: C[128x128] = A @ B^T (+bias).  cp.async 4-stage + ldmatrix.
// (unchanged from R5)
// ---------------------------------------------------------------------------
#define NCHUNK (DD/16)   // 64
#define TILEB 8192
#define STGB  16384
#define GEMM_SMEM (4*STGB)   // 64 KB

template<int MODE>
__global__ __launch_bounds__(256, 2) void mma_gemm(
    const float* __restrict__ bq_, const float* __restrict__ bk_,
    const float* __restrict__ bv_, float* __restrict__ outp)
{
    extern __shared__ char smc[];
    uint32_t sbase = smem_u32(smc);

    const int tid  = threadIdx.x;
    const int wid  = tid >> 5, lane = tid & 31;
    const int wm   = wid >> 2, wn = wid & 3;
    const int bm   = blockIdx.y * 128, bn = blockIdx.x * 128;
    const int qr   = lane >> 2, qc = lane & 3;

    const uint32_t *Asrc, *W; const float* bias;
    if (MODE == 0) {
        int z = blockIdx.z;
        Asrc = (z == 0) ? g_Xq : (z == 1) ? g_Xk : g_Xv;
        W    = (z == 0) ? g_Wq : (z == 1) ? g_Wk : g_Wv;
        bias = (z == 0) ? bq_ : (z == 1) ? bk_ : bv_;
    } else {
        Asrc = g_A; W = g_Wo; bias = bq_;
    }

    const int r0 = tid >> 2, kb = tid & 3;
    const int r1 = r0 + 64;
    const uint32_t dA0 = (uint32_t)(r0 * 64 + ((kb * 16) ^ (((r0 >> 1) & 3) << 4)));
    const uint32_t dA1 = (uint32_t)(r1 * 64 + ((kb * 16) ^ (((r1 >> 1) & 3) << 4)));

    const int g2 = lane >> 3, l7 = lane & 7;
    uint32_t offA[4][2], offB[2][2];
    #pragma unroll
    for (int mi = 0; mi < 4; mi++) {
        int row = wm * 64 + mi * 16 + (g2 & 1) * 8 + l7;
        int h = g2 >> 1;
        #pragma unroll
        for (int ks = 0; ks < 2; ks++)
            offA[mi][ks] = (uint32_t)(row * 64 + ((ks * 32 + h * 16) ^ (((row >> 1) & 3) << 4)));
    }
    #pragma unroll
    for (int p = 0; p < 2; p++) {
        int row = wn * 32 + p * 16 + (g2 >> 1) * 8 + l7;
        int h = g2 & 1;
        #pragma unroll
        for (int ks = 0; ks < 2; ks++)
            offB[p][ks] = (uint32_t)(TILEB + row * 64 + ((ks * 32 + h * 16) ^ (((row >> 1) & 3) << 4)));
    }

    #define ISSUE(chunk) do { \
        int k0_ = (chunk) * 16; \
        uint32_t sb_ = sbase + ((chunk) & 3) * STGB; \
        const uint32_t *a0_, *a1_; \
        if (MODE == 0) { \
            a0_ = Asrc + (size_t)(bm + r0) * DD + k0_ + kb * 4; \
            a1_ = Asrc + (size_t)(bm + r1) * DD + k0_ + kb * 4; \
        } else { \
            int h_ = k0_ >> 6, d_ = (k0_ & 63) + kb * 4; \
            int gr0_ = bm + r0, gr1_ = bm + r1; \
            a0_ = Asrc + (((size_t)((gr0_ >> 11) * HH + h_) * SS + (gr0_ & 2047)) * DKK + d_); \
            a1_ = Asrc + (((size_t)((gr1_ >> 11) * HH + h_) * SS + (gr1_ & 2047)) * DKK + d_); \
        } \
        cpa16(sb_ + dA0, a0_); \
        cpa16(sb_ + dA1, a1_); \
        cpa16(sb_ + TILEB + dA0, W + (size_t)(bn + r0) * DD + k0_ + kb * 4); \
        cpa16(sb_ + TILEB + dA1, W + (size_t)(bn + r1) * DD + k0_ + kb * 4); \
    } while (0)

    float acc[4][4][4];
    #pragma unroll
    for (int i = 0; i < 4; i++)
        #pragma unroll
        for (int j = 0; j < 4; j++)
            #pragma unroll
            for (int k = 0; k < 4; k++) acc[i][j][k] = 0.f;

    ISSUE(0); CPA_COMMIT();
    ISSUE(1); CPA_COMMIT();
    ISSUE(2); CPA_COMMIT();

    for (int i = 0; i < NCHUNK; i++) {
        CPA_WAIT2();
        __syncthreads();
        if (i + 3 < NCHUNK) ISSUE(i + 3);
        CPA_COMMIT();
        uint32_t base_ = sbase + (i & 3) * STGB;
        #pragma unroll
        for (int ks = 0; ks < 2; ks++) {
            uint32_t af[4][4], bqr[2][4];
            ldsm4(af[0], base_ + offA[0][ks]);
            ldsm4(af[1], base_ + offA[1][ks]);
            ldsm4(af[2], base_ + offA[2][ks]);
            ldsm4(af[3], base_ + offA[3][ks]);
            ldsm4(bqr[0], base_ + offB[0][ks]);
            ldsm4(bqr[1], base_ + offB[1][ks]);
            #pragma unroll
            for (int mi = 0; mi < 4; mi++)
                #pragma unroll
                for (int ni = 0; ni < 4; ni++)
                    mma_tf32(acc[mi][ni], af[mi], &bqr[ni >> 1][(ni & 1) * 2]);
        }
    }
    __syncthreads();

    #pragma unroll
    for (int mi = 0; mi < 4; mi++) {
        #pragma unroll
        for (int half = 0; half < 2; half++) {
            int gr = bm + wm * 64 + mi * 16 + qr + half * 8;
            #pragma unroll
            for (int ni = 0; ni < 4; ni++) {
                int cn = bn + wn * 32 + ni * 8 + 2 * qc;
                float v0 = acc[mi][ni][half * 2 + 0] + bias[cn];
                float v1 = acc[mi][ni][half * 2 + 1] + bias[cn + 1];
                if (MODE == 0) {
                    uint32_t* out = (blockIdx.z == 0) ? g_Q : (blockIdx.z == 1) ? g_K : g_V;
                    int b_ = gr >> 11, s_ = gr & 2047;
                    int h_ = cn >> 6,  d_ = cn & 63;
                    uint2* p = (uint2*)(out + (((size_t)(b_ * HH + h_) * SS + s_) * DKK + d_));
                    *p = make_uint2(f2tf32(v0), f2tf32(v1));
                } else {
                    float2* p = (float2*)(outp + (size_t)gr * DD + cn);
                    *p = make_float2(v0, v1);
                }
            }
        }
    }
}

// ---------------------------------------------------------------------------
// Attention, mma.sync tf32.  Block = 128 q rows of one (b,h); 8 warps.
// cp.async double-buffered K/V staging; ldmatrix K-fragments.
// smem: 2 stages x (K 64x68 + V 64x68) words = 69632 B (dynamic).
// ---------------------------------------------------------------------------
#define ATP 68
#define STG_W (2*64*ATP)            // words per stage (K then V)
#define ATTN_SMEM (2*STG_W*4)       // 69632 bytes
#define NT (SS/64)                  // 32 key tiles

__global__ __launch_bounds__(256, 1) void attn_mma()
{
    extern __shared__ uint32_t smw[];
    uint32_t sbase = smem_u32(smw);

    const int tid  = threadIdx.x;
    const int wid  = tid >> 5, lane = tid & 31;
    const int qr   = lane >> 2, qc = lane & 3;
    const int bh   = blockIdx.y;
    const int q0   = blockIdx.x * 128;
    const int w16  = wid * 16;

    const uint32_t* Qp = g_Q + (size_t)bh * SS * DKK;
    const uint32_t* Kp = g_K + (size_t)bh * SS * DKK;
    const uint32_t* Vp = g_V + (size_t)bh * SS * DKK;
    uint32_t*       Ap = g_A + (size_t)bh * SS * DKK;

    // staging map: row sr (0..63), 16 cols starting at sc16
    const int sr = tid >> 2;
    const int sc16 = (tid & 3) * 16;
    const uint32_t kdst = (uint32_t)((sr * ATP + sc16) * 4);
    const uint32_t vdst = kdst + (uint32_t)(64 * ATP * 4);

    #define ISSUE_KV(kb_) do { \
        uint32_t st_ = ((kb_) & 1) * (STG_W * 4); \
        const uint32_t* Kb_ = Kp + (size_t)(kb_) * 64 * DKK + (size_t)sr * DKK + sc16; \
        const uint32_t* Vb_ = Vp + (size_t)(kb_) * 64 * DKK + (size_t)sr * DKK + sc16; \
        cpa16(sbase + st_ + kdst,      Kb_); \
        cpa16(sbase + st_ + kdst + 16, Kb_ + 4); \
        cpa16(sbase + st_ + kdst + 32, Kb_ + 8); \
        cpa16(sbase + st_ + kdst + 48, Kb_ + 12); \
        cpa16(sbase + st_ + vdst,      Vb_); \
        cpa16(sbase + st_ + vdst + 16, Vb_ + 4); \
        cpa16(sbase + st_ + vdst + 32, Vb_ + 8); \
        cpa16(sbase + st_ + vdst + 48, Vb_ + 12); \
    } while (0)

    // Q fragments (scaled by 1/8 -- exact on tf32), in registers for whole kernel
    uint32_t qf[8][4];
    {
        const uint32_t* Qr0 = Qp + (size_t)(q0 + w16 + qr) * DKK;
        const uint32_t* Qr1 = Qr0 + 8 * DKK;
        #pragma unroll
        for (int ks = 0; ks < 8; ks++) {
            int c = ks * 8 + qc;
            qf[ks][0] = f2tf32(__uint_as_float(Qr0[c])     * 0.125f);
            qf[ks][1] = f2tf32(__uint_as_float(Qr1[c])     * 0.125f);
            qf[ks][2] = f2tf32(__uint_as_float(Qr0[c + 4]) * 0.125f);
            qf[ks][3] = f2tf32(__uint_as_float(Qr1[c + 4]) * 0.125f);
        }
    }

    ISSUE_KV(0); CPA_COMMIT();

    float m0 = -1e30f, m1 = -1e30f, l0 = 0.f, l1 = 0.f;
    float o[8][4];
    #pragma unroll
    for (int i = 0; i < 8; i++)
        #pragma unroll
        for (int j = 0; j < 4; j++) o[i][j] = 0.f;

    // ldmatrix per-lane base offset within K stage (add pair*4352 + ks*32)
    const int lm_m = lane >> 3, lm_l7 = lane & 7;
    const uint32_t lm_base = (uint32_t)((((lm_m >> 1) * 8 + lm_l7) * ATP) * 4 + (lm_m & 1) * 16);

    const int src0 = (lane & 28) | (qc >> 1);
    const int src2 = src0 + 2;
    const int e = qc & 1;

    for (int kb = 0; kb < NT; kb++) {
        if (kb + 1 < NT) { ISSUE_KV(kb + 1); CPA_COMMIT(); CPA_WAIT1(); }
        else             { CPA_WAIT0(); }
        __syncthreads();

        const uint32_t kst = sbase + (uint32_t)((kb & 1) * (STG_W * 4));
        const uint32_t* vsm = smw + (kb & 1) * STG_W + 64 * ATP;

        // S = (Q/8) K^T via ldmatrix B-fragments
        float sc[8][4];
        #pragma unroll
        for (int i = 0; i < 8; i++)
            #pragma unroll
            for (int j = 0; j < 4; j++) sc[i][j] = 0.f;

        #pragma unroll
        for (int ks = 0; ks < 8; ks++) {
            uint32_t bf[8][2];
            #pragma unroll
            for (int p = 0; p < 4; p++)
                ldsm4(&bf[2 * p][0], kst + (uint32_t)(p * 16 * ATP * 4) + lm_base + ks * 32);
            #pragma unroll
            for (int ni = 0; ni < 8; ni++)
                mma_tf32(sc[ni], qf[ks], bf[ni]);
        }

        // online softmax (rows qr -> m0/l0, qr+8 -> m1/l1)
        float mx0 = -1e30f, mx1 = -1e30f;
        #pragma unroll
        for (int ni = 0; ni < 8; ni++) {
            mx0 = fmaxf(mx0, fmaxf(sc[ni][0], sc[ni][1]));
            mx1 = fmaxf(mx1, fmaxf(sc[ni][2], sc[ni][3]));
        }
        mx0 = fmaxf(mx0, __shfl_xor_sync(0xffffffffu, mx0, 1));
        mx0 = fmaxf(mx0, __shfl_xor_sync(0xffffffffu, mx0, 2));
        mx1 = fmaxf(mx1, __shfl_xor_sync(0xffffffffu, mx1, 1));
        mx1 = fmaxf(mx1, __shfl_xor_sync(0xffffffffu, mx1, 2));
        float mn0 = fmaxf(m0, mx0), mn1 = fmaxf(m1, mx1);
        float fac0 = __expf(m0 - mn0), fac1 = __expf(m1 - mn1);
        float rs0 = 0.f, rs1 = 0.f;
        #pragma unroll
        for (int ni = 0; ni < 8; ni++) {
            sc[ni][0] = __expf(sc[ni][0] - mn0);
            sc[ni][1] = __expf(sc[ni][1] - mn0);
            sc[ni][2] = __expf(sc[ni][2] - mn1);
            sc[ni][3] = __expf(sc[ni][3] - mn1);
            rs0 += sc[ni][0] + sc[ni][1];
            rs1 += sc[ni][2] + sc[ni][3];
        }
        rs0 += __shfl_xor_sync(0xffffffffu, rs0, 1);
        rs0 += __shfl_xor_sync(0xffffffffu, rs0, 2);
        rs1 += __shfl_xor_sync(0xffffffffu, rs1, 1);
        rs1 += __shfl_xor_sync(0xffffffffu, rs1, 2);
        l0 = l0 * fac0 + rs0;  m0 = mn0;
        l1 = l1 * fac1 + rs1;  m1 = mn1;
        #pragma unroll
        for (int ni = 0; ni < 8; ni++) {
            o[ni][0] *= fac0; o[ni][1] *= fac0;
            o[ni][2] *= fac1; o[ni][3] *= fac1;
        }

        // O += P V, P->A-frag relayout via intra-quad shuffles
        #pragma unroll
        for (int ks = 0; ks < 8; ks++) {
            float x0 = __shfl_sync(0xffffffffu, sc[ks][0], src0);
            float x1 = __shfl_sync(0xffffffffu, sc[ks][1], src0);
            float y0 = __shfl_sync(0xffffffffu, sc[ks][2], src0);
            float y1 = __shfl_sync(0xffffffffu, sc[ks][3], src0);
            float z0 = __shfl_sync(0xffffffffu, sc[ks][0], src2);
            float z1 = __shfl_sync(0xffffffffu, sc[ks][1], src2);
            float w0 = __shfl_sync(0xffffffffu, sc[ks][2], src2);
            float w1 = __shfl_sync(0xffffffffu, sc[ks][3], src2);
            uint32_t a[4];
            a[0] = f2tf32(e ? x1 : x0);
            a[1] = f2tf32(e ? y1 : y0);
            a[2] = f2tf32(e ? z1 : z0);
            a[3] = f2tf32(e ? w1 : w0);
            #pragma unroll
            for (int ni = 0; ni < 8; ni++) {
                uint32_t b[2];
                b[0] = vsm[(ks * 8 + qc) * ATP + ni * 8 + qr];
                b[1] = vsm[(ks * 8 + qc + 4) * ATP + ni * 8 + qr];
                mma_tf32(o[ni], a, b);
            }
        }
        __syncthreads();
    }

    float inv0 = 1.f / l0, inv1 = 1.f / l1;
    uint32_t* Or0 = Ap + (size_t)(q0 + w16 + qr) * DKK;
    uint32_t* Or1 = Or0 + 8 * DKK;
    #pragma unroll
    for (int ni = 0; ni < 8; ni++) {
        int c = ni * 8 + 2 * qc;
        *(uint2*)(Or0 + c) = make_uint2(f2tf32(o[ni][0] * inv0), f2tf32(o[ni][1] * inv0));
        *(uint2*)(Or1 + c) = make_uint2(f2tf32(o[ni][2] * inv1), f2tf32(o[ni][3] * inv1));
    }
}

// ---------------------------------------------------------------------------
// Input order: 0 query, 1 key, 2 value, 3 Wq, 4 bq, 5 Wk, 6 bk, 7 Wv, 8 bv, 9 Wo, 10 bo
// ---------------------------------------------------------------------------
extern "C" void kernel_launch(void* const* d_in, const int* in_sizes, int n_in,
                              void* d_out, int out_size)
{
    (void)in_sizes; (void)n_in; (void)out_size;
    const float* query = (const float*)d_in[0];
    const float* key_  = (const float*)d_in[1];
    const float* value = (const float*)d_in[2];
    const float* Wq = (const float*)d_in[3];
    const float* bq = (const float*)d_in[4];
    const float* Wk = (const float*)d_in[5];
    const float* bk = (const float*)d_in[6];
    const float* Wv = (const float*)d_in[7];
    const float* bv = (const float*)d_in[8];
    const float* Wo = (const float*)d_in[9];
    const float* bo = (const float*)d_in[10];
    float* out = (float*)d_out;

    cudaFuncSetAttribute(mma_gemm<0>, cudaFuncAttributeMaxDynamicSharedMemorySize, GEMM_SMEM);
    cudaFuncSetAttribute(mma_gemm<1>, cudaFuncAttributeMaxDynamicSharedMemorySize, GEMM_SMEM);
    cudaFuncSetAttribute(attn_mma, cudaFuncAttributeMaxDynamicSharedMemorySize, ATTN_SMEM);

    const int NX4 = MR * DD / 4;     // 2097152
    const int NW4 = DD * DD / 4;     // 262144
    conv_tf32<0><<<NX4 / 1024, 256>>>((const float4*)query, NX4);
    conv_tf32<1><<<NX4 / 1024, 256>>>((const float4*)key_,  NX4);
    conv_tf32<2><<<NX4 / 1024, 256>>>((const float4*)value, NX4);
    conv_tf32<3><<<NW4 / 1024, 256>>>((const float4*)Wq, NW4);
    conv_tf32<4><<<NW4 / 1024, 256>>>((const float4*)Wk, NW4);
    conv_tf32<5><<<NW4 / 1024, 256>>>((const float4*)Wv, NW4);
    conv_tf32<6><<<NW4 / 1024, 256>>>((const float4*)Wo, NW4);

    mma_gemm<0><<<dim3(DD/128, MR/128, 3), 256, GEMM_SMEM>>>(bq, bk, bv, nullptr);
    attn_mma<<<dim3(SS/128, BB*HH), 256, ATTN_SMEM>>>();
    mma_gemm<1><<<dim3(DD/128, MR/128, 1), 256, GEMM_SMEM>>>(bo, nullptr, nullptr, out);
}

// round 12
// speedup vs baseline: 3.7888x; 1.0791x over previous
#include <cuda_runtime.h>
#include <cstdint>

#define BB 4
#define SS 2048
#define HH 16
#define DKK 64
#define DD 1024
#define MR (BB*SS)        // 8192 rows

// tf32-bit scratch (device globals; no allocs)
__device__ uint32_t g_Xq[(size_t)MR*DD];
__device__ uint32_t g_Xk[(size_t)MR*DD];
__device__ uint32_t g_Xv[(size_t)MR*DD];
__device__ uint32_t g_Wq[(size_t)DD*DD];
__device__ uint32_t g_Wk[(size_t)DD*DD];
__device__ uint32_t g_Wv[(size_t)DD*DD];
__device__ uint32_t g_Wo[(size_t)DD*DD];
__device__ uint32_t g_Q[(size_t)BB*HH*SS*DKK];
__device__ uint32_t g_K[(size_t)BB*HH*SS*DKK];
__device__ uint32_t g_V[(size_t)BB*HH*SS*DKK];
__device__ uint32_t g_A[(size_t)BB*HH*SS*DKK];

static __device__ __forceinline__ uint32_t f2tf32(float x) {
    uint32_t u;
    asm("cvt.rna.tf32.f32 %0, %1;" : "=r"(u) : "f"(x));
    return u;
}

static __device__ __forceinline__ void mma_tf32(float c[4],
                                                const uint32_t a[4],
                                                const uint32_t b[2]) {
    asm volatile(
        "mma.sync.aligned.m16n8k8.row.col.f32.tf32.tf32.f32 "
        "{%0,%1,%2,%3}, {%4,%5,%6,%7}, {%8,%9}, {%0,%1,%2,%3};"
        : "+f"(c[0]), "+f"(c[1]), "+f"(c[2]), "+f"(c[3])
        : "r"(a[0]), "r"(a[1]), "r"(a[2]), "r"(a[3]), "r"(b[0]), "r"(b[1]));
}

static __device__ __forceinline__ uint32_t smem_u32(const void* p) {
    uint32_t a;
    asm("{ .reg .u64 t; cvta.to.shared.u64 t, %1; cvt.u32.u64 %0, t; }" : "=r"(a) : "l"(p));
    return a;
}
static __device__ __forceinline__ void cpa16(uint32_t s, const void* g) {
    asm volatile("cp.async.cg.shared.global [%0], [%1], 16;" :: "r"(s), "l"(g) : "memory");
}
#define CPA_COMMIT() asm volatile("cp.async.commit_group;" ::: "memory")
#define CPA_WAIT2()  asm volatile("cp.async.wait_group 2;" ::: "memory")
#define CPA_WAIT1()  asm volatile("cp.async.wait_group 1;" ::: "memory")
#define CPA_WAIT0()  asm volatile("cp.async.wait_group 0;" ::: "memory")

static __device__ __forceinline__ void ldsm4(uint32_t d[4], uint32_t addr) {
    asm volatile("ldmatrix.sync.aligned.m8n8.x4.shared.b16 {%0,%1,%2,%3}, [%4];"
                 : "=r"(d[0]), "=r"(d[1]), "=r"(d[2]), "=r"(d[3]) : "r"(addr));
}

// ---------------------------------------------------------------------------
// fp32 -> tf32(RNA) conversions
// X arrays: ILP 8, grid 1024.  W arrays: one fused launch, grid (256,4), ILP 4.
// ---------------------------------------------------------------------------
template<int SEL>
__global__ void conv_x(const float4* __restrict__ src)
{
    uint32_t* dst = (SEL == 0) ? g_Xq : (SEL == 1) ? g_Xk : g_Xv;
    int base = blockIdx.x * (blockDim.x * 8) + threadIdx.x;
    float4 v[8];
    #pragma unroll
    for (int j = 0; j < 8; j++) v[j] = src[base + j * 256];
    #pragma unroll
    for (int j = 0; j < 8; j++)
        ((uint4*)dst)[base + j * 256] =
            make_uint4(f2tf32(v[j].x), f2tf32(v[j].y), f2tf32(v[j].z), f2tf32(v[j].w));
}

__global__ void conv_w(const float4* __restrict__ wq, const float4* __restrict__ wk,
                       const float4* __restrict__ wv, const float4* __restrict__ wo)
{
    int z = blockIdx.y;
    const float4* src = (z == 0) ? wq : (z == 1) ? wk : (z == 2) ? wv : wo;
    uint32_t* dst = (z == 0) ? g_Wq : (z == 1) ? g_Wk : (z == 2) ? g_Wv : g_Wo;
    int base = blockIdx.x * (blockDim.x * 4) + threadIdx.x;
    float4 v[4];
    #pragma unroll
    for (int j = 0; j < 4; j++) v[j] = src[base + j * 256];
    #pragma unroll
    for (int j = 0; j < 4; j++)
        ((uint4*)dst)[base + j * 256] =
            make_uint4(f2tf32(v[j].x), f2tf32(v[j].y), f2tf32(v[j].z), f2tf32(v[j].w));
}

// ---------------------------------------------------------------------------
// tf32 GEMM: C[128x128] = A @ B^T (+bias).  cp.async 4-stage + ldmatrix.
// ---------------------------------------------------------------------------
#define NCHUNK (DD/16)   // 64
#define TILEB 8192
#define STGB  16384
#define GEMM_SMEM (4*STGB)   // 64 KB

template<int MODE>
__global__ __launch_bounds__(256, 2) void mma_gemm(
    const float* __restrict__ bq_, const float* __restrict__ bk_,
    const float* __restrict__ bv_, float* __restrict__ outp)
{
    extern __shared__ char smc[];
    uint32_t sbase = smem_u32(smc);

    const int tid  = threadIdx.x;
    const int wid  = tid >> 5, lane = tid & 31;
    const int wm   = wid >> 2, wn = wid & 3;
    const int bm   = blockIdx.y * 128, bn = blockIdx.x * 128;
    const int qr   = lane >> 2, qc = lane & 3;

    const uint32_t *Asrc, *W; const float* bias;
    if (MODE == 0) {
        int z = blockIdx.z;
        Asrc = (z == 0) ? g_Xq : (z == 1) ? g_Xk : g_Xv;
        W    = (z == 0) ? g_Wq : (z == 1) ? g_Wk : g_Wv;
        bias = (z == 0) ? bq_ : (z == 1) ? bk_ : bv_;
    } else {
        Asrc = g_A; W = g_Wo; bias = bq_;
    }

    const int r0 = tid >> 2, kb = tid & 3;
    const int r1 = r0 + 64;
    const uint32_t dA0 = (uint32_t)(r0 * 64 + ((kb * 16) ^ (((r0 >> 1) & 3) << 4)));
    const uint32_t dA1 = (uint32_t)(r1 * 64 + ((kb * 16) ^ (((r1 >> 1) & 3) << 4)));

    const int g2 = lane >> 3, l7 = lane & 7;
    uint32_t offA[4][2], offB[2][2];
    #pragma unroll
    for (int mi = 0; mi < 4; mi++) {
        int row = wm * 64 + mi * 16 + (g2 & 1) * 8 + l7;
        int h = g2 >> 1;
        #pragma unroll
        for (int ks = 0; ks < 2; ks++)
            offA[mi][ks] = (uint32_t)(row * 64 + ((ks * 32 + h * 16) ^ (((row >> 1) & 3) << 4)));
    }
    #pragma unroll
    for (int p = 0; p < 2; p++) {
        int row = wn * 32 + p * 16 + (g2 >> 1) * 8 + l7;
        int h = g2 & 1;
        #pragma unroll
        for (int ks = 0; ks < 2; ks++)
            offB[p][ks] = (uint32_t)(TILEB + row * 64 + ((ks * 32 + h * 16) ^ (((row >> 1) & 3) << 4)));
    }

    #define ISSUE(chunk) do { \
        int k0_ = (chunk) * 16; \
        uint32_t sb_ = sbase + ((chunk) & 3) * STGB; \
        const uint32_t *a0_, *a1_; \
        if (MODE == 0) { \
            a0_ = Asrc + (size_t)(bm + r0) * DD + k0_ + kb * 4; \
            a1_ = Asrc + (size_t)(bm + r1) * DD + k0_ + kb * 4; \
        } else { \
            int h_ = k0_ >> 6, d_ = (k0_ & 63) + kb * 4; \
            int gr0_ = bm + r0, gr1_ = bm + r1; \
            a0_ = Asrc + (((size_t)((gr0_ >> 11) * HH + h_) * SS + (gr0_ & 2047)) * DKK + d_); \
            a1_ = Asrc + (((size_t)((gr1_ >> 11) * HH + h_) * SS + (gr1_ & 2047)) * DKK + d_); \
        } \
        cpa16(sb_ + dA0, a0_); \
        cpa16(sb_ + dA1, a1_); \
        cpa16(sb_ + TILEB + dA0, W + (size_t)(bn + r0) * DD + k0_ + kb * 4); \
        cpa16(sb_ + TILEB + dA1, W + (size_t)(bn + r1) * DD + k0_ + kb * 4); \
    } while (0)

    float acc[4][4][4];
    #pragma unroll
    for (int i = 0; i < 4; i++)
        #pragma unroll
        for (int j = 0; j < 4; j++)
            #pragma unroll
            for (int k = 0; k < 4; k++) acc[i][j][k] = 0.f;

    ISSUE(0); CPA_COMMIT();
    ISSUE(1); CPA_COMMIT();
    ISSUE(2); CPA_COMMIT();

    for (int i = 0; i < NCHUNK; i++) {
        CPA_WAIT2();
        __syncthreads();
        if (i + 3 < NCHUNK) ISSUE(i + 3);
        CPA_COMMIT();
        uint32_t base_ = sbase + (i & 3) * STGB;
        #pragma unroll
        for (int ks = 0; ks < 2; ks++) {
            uint32_t af[4][4], bqr[2][4];
            ldsm4(af[0], base_ + offA[0][ks]);
            ldsm4(af[1], base_ + offA[1][ks]);
            ldsm4(af[2], base_ + offA[2][ks]);
            ldsm4(af[3], base_ + offA[3][ks]);
            ldsm4(bqr[0], base_ + offB[0][ks]);
            ldsm4(bqr[1], base_ + offB[1][ks]);
            #pragma unroll
            for (int mi = 0; mi < 4; mi++)
                #pragma unroll
                for (int ni = 0; ni < 4; ni++)
                    mma_tf32(acc[mi][ni], af[mi], &bqr[ni >> 1][(ni & 1) * 2]);
        }
    }
    __syncthreads();

    #pragma unroll
    for (int mi = 0; mi < 4; mi++) {
        #pragma unroll
        for (int half = 0; half < 2; half++) {
            int gr = bm + wm * 64 + mi * 16 + qr + half * 8;
            #pragma unroll
            for (int ni = 0; ni < 4; ni++) {
                int cn = bn + wn * 32 + ni * 8 + 2 * qc;
                float v0 = acc[mi][ni][half * 2 + 0] + bias[cn];
                float v1 = acc[mi][ni][half * 2 + 1] + bias[cn + 1];
                if (MODE == 0) {
                    uint32_t* out = (blockIdx.z == 0) ? g_Q : (blockIdx.z == 1) ? g_K : g_V;
                    int b_ = gr >> 11, s_ = gr & 2047;
                    int h_ = cn >> 6,  d_ = cn & 63;
                    uint2* p = (uint2*)(out + (((size_t)(b_ * HH + h_) * SS + s_) * DKK + d_));
                    *p = make_uint2(f2tf32(v0), f2tf32(v1));
                } else {
                    float2* p = (float2*)(outp + (size_t)gr * DD + cn);
                    *p = make_float2(v0, v1);
                }
            }
        }
    }
}

// ---------------------------------------------------------------------------
// Attention, mma.sync tf32.  Block = 128 q rows of one (b,h); 8 warps.
// cp.async double-buffered K/V; ldmatrix K-frags; V pitch 72 (conflict-free);
// scores pre-scaled by log2(e) -> exp2f softmax.
// ---------------------------------------------------------------------------
#define KP 68
#define VP 72
#define STG_W (64*KP + 64*VP)       // words per stage
#define ATTN_SMEM (2*STG_W*4)       // 71680 bytes
#define NT (SS/64)                  // 32 key tiles
#define QSCALE 0.18033688011112042f // 0.125 * log2(e)

__global__ __launch_bounds__(256, 1) void attn_mma()
{
    extern __shared__ uint32_t smw[];
    uint32_t sbase = smem_u32(smw);

    const int tid  = threadIdx.x;
    const int wid  = tid >> 5, lane = tid & 31;
    const int qr   = lane >> 2, qc = lane & 3;
    const int bh   = blockIdx.y;
    const int q0   = blockIdx.x * 128;
    const int w16  = wid * 16;

    const uint32_t* Qp = g_Q + (size_t)bh * SS * DKK;
    const uint32_t* Kp = g_K + (size_t)bh * SS * DKK;
    const uint32_t* Vp = g_V + (size_t)bh * SS * DKK;
    uint32_t*       Ap = g_A + (size_t)bh * SS * DKK;

    const int sr = tid >> 2;
    const int sc16 = (tid & 3) * 16;
    const uint32_t kdst = (uint32_t)((sr * KP + sc16) * 4);
    const uint32_t vdst = (uint32_t)(64 * KP * 4 + (sr * VP + sc16) * 4);

    #define ISSUE_KV(kb_) do { \
        uint32_t st_ = ((kb_) & 1) * (STG_W * 4); \
        const uint32_t* Kb_ = Kp + (size_t)(kb_) * 64 * DKK + (size_t)sr * DKK + sc16; \
        const uint32_t* Vb_ = Vp + (size_t)(kb_) * 64 * DKK + (size_t)sr * DKK + sc16; \
        cpa16(sbase + st_ + kdst,      Kb_); \
        cpa16(sbase + st_ + kdst + 16, Kb_ + 4); \
        cpa16(sbase + st_ + kdst + 32, Kb_ + 8); \
        cpa16(sbase + st_ + kdst + 48, Kb_ + 12); \
        cpa16(sbase + st_ + vdst,      Vb_); \
        cpa16(sbase + st_ + vdst + 16, Vb_ + 4); \
        cpa16(sbase + st_ + vdst + 32, Vb_ + 8); \
        cpa16(sbase + st_ + vdst + 48, Vb_ + 12); \
    } while (0)

    // Q fragments scaled by 0.125*log2(e): scores come out in log2 domain
    uint32_t qf[8][4];
    {
        const uint32_t* Qr0 = Qp + (size_t)(q0 + w16 + qr) * DKK;
        const uint32_t* Qr1 = Qr0 + 8 * DKK;
        #pragma unroll
        for (int ks = 0; ks < 8; ks++) {
            int c = ks * 8 + qc;
            qf[ks][0] = f2tf32(__uint_as_float(Qr0[c])     * QSCALE);
            qf[ks][1] = f2tf32(__uint_as_float(Qr1[c])     * QSCALE);
            qf[ks][2] = f2tf32(__uint_as_float(Qr0[c + 4]) * QSCALE);
            qf[ks][3] = f2tf32(__uint_as_float(Qr1[c + 4]) * QSCALE);
        }
    }

    ISSUE_KV(0); CPA_COMMIT();

    float m0 = -1e30f, m1 = -1e30f, l0 = 0.f, l1 = 0.f;
    float o[8][4];
    #pragma unroll
    for (int i = 0; i < 8; i++)
        #pragma unroll
        for (int j = 0; j < 4; j++) o[i][j] = 0.f;

    const int lm_m = lane >> 3, lm_l7 = lane & 7;
    const uint32_t lm_base = (uint32_t)((((lm_m >> 1) * 8 + lm_l7) * KP) * 4 + (lm_m & 1) * 16);

    const int src0 = (lane & 28) | (qc >> 1);
    const int src2 = src0 + 2;
    const int e = qc & 1;

    for (int kb = 0; kb < NT; kb++) {
        if (kb + 1 < NT) { ISSUE_KV(kb + 1); CPA_COMMIT(); CPA_WAIT1(); }
        else             { CPA_WAIT0(); }
        __syncthreads();

        const uint32_t kst = sbase + (uint32_t)((kb & 1) * (STG_W * 4));
        const uint32_t* vsm = smw + (kb & 1) * STG_W + 64 * KP;

        float sc[8][4];
        #pragma unroll
        for (int i = 0; i < 8; i++)
            #pragma unroll
            for (int j = 0; j < 4; j++) sc[i][j] = 0.f;

        #pragma unroll
        for (int ks = 0; ks < 8; ks++) {
            uint32_t bf[8][2];
            #pragma unroll
            for (int p = 0; p < 4; p++)
                ldsm4(&bf[2 * p][0], kst + (uint32_t)(p * 16 * KP * 4) + lm_base + ks * 32);
            #pragma unroll
            for (int ni = 0; ni < 8; ni++)
                mma_tf32(sc[ni], qf[ks], bf[ni]);
        }

        // online softmax in log2 domain
        float mx0 = -1e30f, mx1 = -1e30f;
        #pragma unroll
        for (int ni = 0; ni < 8; ni++) {
            mx0 = fmaxf(mx0, fmaxf(sc[ni][0], sc[ni][1]));
            mx1 = fmaxf(mx1, fmaxf(sc[ni][2], sc[ni][3]));
        }
        mx0 = fmaxf(mx0, __shfl_xor_sync(0xffffffffu, mx0, 1));
        mx0 = fmaxf(mx0, __shfl_xor_sync(0xffffffffu, mx0, 2));
        mx1 = fmaxf(mx1, __shfl_xor_sync(0xffffffffu, mx1, 1));
        mx1 = fmaxf(mx1, __shfl_xor_sync(0xffffffffu, mx1, 2));
        float mn0 = fmaxf(m0, mx0), mn1 = fmaxf(m1, mx1);
        float fac0 = exp2f(m0 - mn0), fac1 = exp2f(m1 - mn1);
        float rs0 = 0.f, rs1 = 0.f;
        #pragma unroll
        for (int ni = 0; ni < 8; ni++) {
            sc[ni][0] = exp2f(sc[ni][0] - mn0);
            sc[ni][1] = exp2f(sc[ni][1] - mn0);
            sc[ni][2] = exp2f(sc[ni][2] - mn1);
            sc[ni][3] = exp2f(sc[ni][3] - mn1);
            rs0 += sc[ni][0] + sc[ni][1];
            rs1 += sc[ni][2] + sc[ni][3];
        }
        rs0 += __shfl_xor_sync(0xffffffffu, rs0, 1);
        rs0 += __shfl_xor_sync(0xffffffffu, rs0, 2);
        rs1 += __shfl_xor_sync(0xffffffffu, rs1, 1);
        rs1 += __shfl_xor_sync(0xffffffffu, rs1, 2);
        l0 = l0 * fac0 + rs0;  m0 = mn0;
        l1 = l1 * fac1 + rs1;  m1 = mn1;
        #pragma unroll
        for (int ni = 0; ni < 8; ni++) {
            o[ni][0] *= fac0; o[ni][1] *= fac0;
            o[ni][2] *= fac1; o[ni][3] *= fac1;
        }

        // O += P V
        #pragma unroll
        for (int ks = 0; ks < 8; ks++) {
            float x0 = __shfl_sync(0xffffffffu, sc[ks][0], src0);
            float x1 = __shfl_sync(0xffffffffu, sc[ks][1], src0);
            float y0 = __shfl_sync(0xffffffffu, sc[ks][2], src0);
            float y1 = __shfl_sync(0xffffffffu, sc[ks][3], src0);
            float z0 = __shfl_sync(0xffffffffu, sc[ks][0], src2);
            float z1 = __shfl_sync(0xffffffffu, sc[ks][1], src2);
            float w0 = __shfl_sync(0xffffffffu, sc[ks][2], src2);
            float w1 = __shfl_sync(0xffffffffu, sc[ks][3], src2);
            uint32_t a[4];
            a[0] = f2tf32(e ? x1 : x0);
            a[1] = f2tf32(e ? y1 : y0);
            a[2] = f2tf32(e ? z1 : z0);
            a[3] = f2tf32(e ? w1 : w0);
            #pragma unroll
            for (int ni = 0; ni < 8; ni++) {
                uint32_t b[2];
                b[0] = vsm[(ks * 8 + qc) * VP + ni * 8 + qr];
                b[1] = vsm[(ks * 8 + qc + 4) * VP + ni * 8 + qr];
                mma_tf32(o[ni], a, b);
            }
        }
        __syncthreads();
    }

    float inv0 = 1.f / l0, inv1 = 1.f / l1;
    uint32_t* Or0 = Ap + (size_t)(q0 + w16 + qr) * DKK;
    uint32_t* Or1 = Or0 + 8 * DKK;
    #pragma unroll
    for (int ni = 0; ni < 8; ni++) {
        int c = ni * 8 + 2 * qc;
        *(uint2*)(Or0 + c) = make_uint2(f2tf32(o[ni][0] * inv0), f2tf32(o[ni][1] * inv0));
        *(uint2*)(Or1 + c) = make_uint2(f2tf32(o[ni][2] * inv1), f2tf32(o[ni][3] * inv1));
    }
}

// ---------------------------------------------------------------------------
// Input order: 0 query, 1 key, 2 value, 3 Wq, 4 bq, 5 Wk, 6 bk, 7 Wv, 8 bv, 9 Wo, 10 bo
// ---------------------------------------------------------------------------
extern "C" void kernel_launch(void* const* d_in, const int* in_sizes, int n_in,
                              void* d_out, int out_size)
{
    (void)in_sizes; (void)n_in; (void)out_size;
    const float* query = (const float*)d_in[0];
    const float* key_  = (const float*)d_in[1];
    const float* value = (const float*)d_in[2];
    const float* Wq = (const float*)d_in[3];
    const float* bq = (const float*)d_in[4];
    const float* Wk = (const float*)d_in[5];
    const float* bk = (const float*)d_in[6];
    const float* Wv = (const float*)d_in[7];
    const float* bv = (const float*)d_in[8];
    const float* Wo = (const float*)d_in[9];
    const float* bo = (const float*)d_in[10];
    float* out = (float*)d_out;

    cudaFuncSetAttribute(mma_gemm<0>, cudaFuncAttributeMaxDynamicSharedMemorySize, GEMM_SMEM);
    cudaFuncSetAttribute(mma_gemm<1>, cudaFuncAttributeMaxDynamicSharedMemorySize, GEMM_SMEM);
    cudaFuncSetAttribute(attn_mma, cudaFuncAttributeMaxDynamicSharedMemorySize, ATTN_SMEM);

    conv_x<0><<<1024, 256>>>((const float4*)query);
    conv_x<1><<<1024, 256>>>((const float4*)key_);
    conv_x<2><<<1024, 256>>>((const float4*)value);
    conv_w<<<dim3(256, 4), 256>>>((const float4*)Wq, (const float4*)Wk,
                                  (const float4*)Wv, (const float4*)Wo);

    mma_gemm<0><<<dim3(DD/128, MR/128, 3), 256, GEMM_SMEM>>>(bq, bk, bv, nullptr);
    attn_mma<<<dim3(SS/128, BB*HH), 256, ATTN_SMEM>>>();
    mma_gemm<1><<<dim3(DD/128, MR/128, 1), 256, GEMM_SMEM>>>(bo, nullptr, nullptr, out);
}